// round 5
// baseline (speedup 1.0000x reference)
#include <cuda_runtime.h>
#include <math.h>

#define TT 512
#define BB 64
#define CC 256
#define HH 1024
#define RR (TT*BB)

#define WPAD 36
#define NB_RNN 128
#define RED_ULL_STRIDE 258
#define RNN_SMEM (1024*WPAD*4 + 32*RED_ULL_STRIDE*8)   // 213504 bytes

typedef unsigned long long ull;

// ---------------- packed fp32x2 helpers ----------------
#define PACKDUP(d, s) asm("mov.b64 %0, {%1, %1};" : "=l"(d) : "r"(__float_as_uint(s)))
#define FFMA2(acc, a, b) asm("fma.rn.f32x2 %0, %1, %2, %0;" : "+l"(acc) : "l"(a), "l"(b))
#define ADD2(d, a, b) asm("add.rn.f32x2 %0, %1, %2;" : "=l"(d) : "l"(a), "l"(b))
#define UNPACK2(lo, hi, v) asm("mov.b64 {%0, %1}, %2;" : "=r"(lo), "=r"(hi) : "l"(v))

// ---------------- scratch ----------------
__device__ float g_xw[(size_t)TT*BB*HH];
__device__ float g_y0[(size_t)TT*BB*HH];
__device__ float g_y1[(size_t)TT*BB*HH];

// ---------------- tree grid barrier (monotonic counters, no resets) --------
// 8 leaf counters (256B apart -> distinct LTS slices), 16 CTAs/leaf, 1 root.
__device__ unsigned g_leaf[8*64];   // stride 64 uints = 256 B
__device__ unsigned g_root = 0;
__device__ unsigned g_gen  = 0;

__device__ __forceinline__ unsigned read_gen_relaxed() {
    unsigned v;
    asm volatile("ld.relaxed.gpu.global.u32 %0, [%1];"
                 : "=r"(v) : "l"(&g_gen) : "memory");
    return v;
}

__device__ __forceinline__ void grid_sync_tree(unsigned gen_target, unsigned* leaf) {
    __syncthreads();
    if (threadIdx.x == 0) {
        unsigned old;
        asm volatile("atom.acq_rel.gpu.global.add.u32 %0, [%1], 1;"
                     : "=r"(old) : "l"(leaf) : "memory");
        if (old + 1u == 16u * gen_target) {
            asm volatile("atom.acq_rel.gpu.global.add.u32 %0, [%1], 1;"
                         : "=r"(old) : "l"(&g_root) : "memory");
            if (old + 1u == 8u * gen_target) {
                asm volatile("st.release.gpu.global.u32 [%0], %1;"
                             :: "l"(&g_gen), "r"(gen_target) : "memory");
            }
        }
        unsigned v;
        do {
            asm volatile("ld.acquire.gpu.global.u32 %0, [%1];"
                         : "=r"(v) : "l"(&g_gen) : "memory");
        } while ((int)(v - gen_target) < 0);
    }
    __syncthreads();
}

// ---------------- parallel GEMM: out[R,N] = A[R,K] @ W[N,K]^T + b1(+b2) ----
__global__ __launch_bounds__(256) void gemm_bias_kernel(
    const float* __restrict__ A, const float* __restrict__ W,
    const float* __restrict__ b1, const float* __restrict__ b2,
    float* __restrict__ out, int R, int N, int K)
{
    __shared__ float As[16][132];
    __shared__ float Ws[16][132];
    const int tid  = threadIdx.x;
    const int r0   = blockIdx.y * 128;
    const int c0   = blockIdx.x * 128;
    const int lr   = tid >> 1;
    const int lq   = (tid & 1) * 4;
    const int lane = tid & 31;
    const int w    = tid >> 5;
    const int tx = ((w & 1) << 3) + (lane & 7);
    const int ty = ((w >> 1) << 2) + (lane >> 3);

    ull acc2[8][4];
    #pragma unroll
    for (int i = 0; i < 8; i++)
        #pragma unroll
        for (int c = 0; c < 4; c++) acc2[i][c] = 0ull;

    const float* Arow = A + (size_t)(r0 + lr) * K;
    const float* Wrow = W + (size_t)(c0 + lr) * K;

    for (int k0 = 0; k0 < K; k0 += 16) {
        #pragma unroll
        for (int l = 0; l < 2; l++) {
            float4 av = *(const float4*)(Arow + k0 + l*8 + lq);
            float4 wv = *(const float4*)(Wrow + k0 + l*8 + lq);
            int kk = l*8 + lq;
            As[kk+0][lr] = av.x;  As[kk+1][lr] = av.y;
            As[kk+2][lr] = av.z;  As[kk+3][lr] = av.w;
            Ws[kk+0][lr] = wv.x;  Ws[kk+1][lr] = wv.y;
            Ws[kk+2][lr] = wv.z;  Ws[kk+3][lr] = wv.w;
        }
        __syncthreads();
        #pragma unroll
        for (int kk = 0; kk < 16; kk++) {
            float4 a0 = *(const float4*)&As[kk][ty*8];
            float4 a1 = *(const float4*)&As[kk][ty*8+4];
            ulonglong2 wv0 = *(const ulonglong2*)&Ws[kk][tx*8];
            ulonglong2 wv1 = *(const ulonglong2*)&Ws[kk][tx*8+4];
            ull wp0 = wv0.x, wp1 = wv0.y, wp2 = wv1.x, wp3 = wv1.y;
            float av8[8] = {a0.x,a0.y,a0.z,a0.w,a1.x,a1.y,a1.z,a1.w};
            #pragma unroll
            for (int i = 0; i < 8; i++) {
                ull ad; PACKDUP(ad, av8[i]);
                FFMA2(acc2[i][0], ad, wp0);
                FFMA2(acc2[i][1], ad, wp1);
                FFMA2(acc2[i][2], ad, wp2);
                FFMA2(acc2[i][3], ad, wp3);
            }
        }
        __syncthreads();
    }

    float bias[8];
    #pragma unroll
    for (int j = 0; j < 8; j++) {
        int col = c0 + tx*8 + j;
        bias[j] = b1[col] + (b2 ? b2[col] : 0.f);
    }
    #pragma unroll
    for (int i = 0; i < 8; i++) {
        float o[8];
        #pragma unroll
        for (int c = 0; c < 4; c++) {
            unsigned lo, hi;
            UNPACK2(lo, hi, acc2[i][c]);
            o[2*c]   = __uint_as_float(lo) + bias[2*c];
            o[2*c+1] = __uint_as_float(hi) + bias[2*c+1];
        }
        int row = r0 + ty*8 + i;
        *(float4*)(out + (size_t)row*N + c0 + tx*8)     = make_float4(o[0],o[1],o[2],o[3]);
        *(float4*)(out + (size_t)row*N + c0 + tx*8 + 4) = make_float4(o[4],o[5],o[6],o[7]);
    }
}

// ------------- persistent recurrence: y[t]=tanh(xw[t]+h_{t-1}@Whh^T) -------
__global__ __launch_bounds__(256) void rnn_layer_kernel(
    const float* __restrict__ xw, const float* __restrict__ h0,
    const float* __restrict__ Whh, float* __restrict__ y, int nsteps)
{
    extern __shared__ float smem[];
    float* Wsh = smem;                 // [1024][WPAD] transposed W slice
    float* hsm = smem + 1024*WPAD;     // [1024][16] transposed h; reused for reduce
    ull*   red2 = (ull*)hsm;

    const int tid = threadIdx.x;
    const int bid = blockIdx.x;
    const int cg  = bid & 31;
    const int bg  = bid >> 5;
    const int c0  = cg * 32;
    unsigned* myleaf = &g_leaf[(bid & 7) * 64];

    // starting generation (safe: gen can't advance until every CTA arrives,
    // and every CTA reads before its first arrival)
    unsigned gen0 = read_gen_relaxed();

    // one-time W slice load, transposed: Wsh[k][j_local]
    {
        const int j  = tid & 31;
        const int kc = tid >> 5;
        const float* wr = Whh + (size_t)(c0 + j) * HH + kc*128;
        #pragma unroll
        for (int i = 0; i < 32; i++) {
            float4 v = *(const float4*)(wr + i*4);
            int k = kc*128 + i*4;
            Wsh[(k+0)*WPAD + j] = v.x;
            Wsh[(k+1)*WPAD + j] = v.y;
            Wsh[(k+2)*WPAD + j] = v.z;
            Wsh[(k+3)*WPAD + j] = v.w;
        }
    }
    __syncthreads();   // W ready; hsm free

    const int hb   = tid & 15;
    const int hkc  = tid >> 4;
    const int tile = tid & 7;
    const int kg   = tid >> 3;
    const int bl0  = (tile >> 2) * 8;
    const int jl0  = (tile & 3) * 8;
    // epilogue output mapping (fixed per thread)
    const int eb   = tid >> 4;          // batch-local 0..15
    const int ej   = (tid & 15) * 2;    // col pair

    for (int t = 0; t < nsteps; t++) {
        const float* hprev = (t == 0) ? h0 : (y + (size_t)(t-1)*BB*HH);

        // prefetch epilogue operand (depends only on t)
        size_t oidx = ((size_t)t*BB + bg*16 + eb)*HH + c0 + ej;
        float2 xwv = *(const float2*)&xw[oidx];

        // load h tile transposed: hsm[k][b_local]
        {
            const float* hr = hprev + (size_t)(bg*16 + hb)*HH + hkc*64;
            #pragma unroll
            for (int i = 0; i < 16; i++) {
                float4 v = *(const float4*)(hr + i*4);
                int k = hkc*64 + i*4;
                hsm[(k+0)*16 + hb] = v.x;
                hsm[(k+1)*16 + hb] = v.y;
                hsm[(k+2)*16 + hb] = v.z;
                hsm[(k+3)*16 + hb] = v.w;
            }
        }
        __syncthreads();

        ull acc2[8][4];
        #pragma unroll
        for (int r = 0; r < 8; r++)
            #pragma unroll
            for (int c = 0; c < 4; c++) acc2[r][c] = 0ull;

        #pragma unroll 2
        for (int i = 0; i < 32; i++) {
            int k = i*32 + kg;
            float4 h0v = *(const float4*)&hsm[k*16 + bl0];
            float4 h1v = *(const float4*)&hsm[k*16 + bl0 + 4];
            ulonglong2 wv0 = *(const ulonglong2*)&Wsh[k*WPAD + jl0];
            ulonglong2 wv1 = *(const ulonglong2*)&Wsh[k*WPAD + jl0 + 4];
            ull wp0 = wv0.x, wp1 = wv0.y, wp2 = wv1.x, wp3 = wv1.y;
            float hv[8] = {h0v.x,h0v.y,h0v.z,h0v.w,h1v.x,h1v.y,h1v.z,h1v.w};
            #pragma unroll
            for (int r = 0; r < 8; r++) {
                ull hd; PACKDUP(hd, hv[r]);
                FFMA2(acc2[r][0], hd, wp0);
                FFMA2(acc2[r][1], hd, wp1);
                FFMA2(acc2[r][2], hd, wp2);
                FFMA2(acc2[r][3], hd, wp3);
            }
        }
        __syncthreads();   // done reading hsm; reuse as reduce buffer

        #pragma unroll
        for (int r = 0; r < 8; r++)
            #pragma unroll
            for (int c = 0; c < 4; c++) {
                int p = (bl0 + r) * 16 + (jl0 >> 1) + c;
                red2[kg*RED_ULL_STRIDE + p] = acc2[r][c];
            }
        __syncthreads();

        {
            ull s0 = red2[tid];
            ull s1 = red2[RED_ULL_STRIDE + tid];
            ull s2 = red2[2*RED_ULL_STRIDE + tid];
            ull s3 = red2[3*RED_ULL_STRIDE + tid];
            #pragma unroll
            for (int g = 4; g < 32; g += 4) {
                ADD2(s0, s0, red2[(g+0)*RED_ULL_STRIDE + tid]);
                ADD2(s1, s1, red2[(g+1)*RED_ULL_STRIDE + tid]);
                ADD2(s2, s2, red2[(g+2)*RED_ULL_STRIDE + tid]);
                ADD2(s3, s3, red2[(g+3)*RED_ULL_STRIDE + tid]);
            }
            ADD2(s0, s0, s1);
            ADD2(s2, s2, s3);
            ADD2(s0, s0, s2);
            unsigned lo, hi;
            UNPACK2(lo, hi, s0);
            float2 rv;
            rv.x = tanhf(xwv.x + __uint_as_float(lo));
            rv.y = tanhf(xwv.y + __uint_as_float(hi));
            *(float2*)&y[oidx] = rv;
        }

        grid_sync_tree(gen0 + (unsigned)t + 1u, myleaf);
    }
}

// ------------- hidden-state gather ----------------
__global__ void gather_hidden_kernel(float* __restrict__ out_hidden)
{
    int i = blockIdx.x * blockDim.x + threadIdx.x;
    const float* src = (i < BB*HH)
        ? (g_y0 + (size_t)(TT-1)*BB*HH + i)
        : (g_y1 + (size_t)(TT-1)*BB*HH + (i - BB*HH));
    out_hidden[i] = *src;
}

extern "C" void kernel_launch(void* const* d_in, const int* in_sizes, int n_in,
                              void* d_out, int out_size) {
    const float* x     = (const float*)d_in[0];
    const float* h0    = (const float*)d_in[1];
    const float* w_ih0 = (const float*)d_in[2];
    const float* w_hh0 = (const float*)d_in[3];
    const float* b_ih0 = (const float*)d_in[4];
    const float* b_hh0 = (const float*)d_in[5];
    const float* w_ih1 = (const float*)d_in[6];
    const float* w_hh1 = (const float*)d_in[7];
    const float* b_ih1 = (const float*)d_in[8];
    const float* b_hh1 = (const float*)d_in[9];
    const float* w_dec = (const float*)d_in[10];
    const float* b_dec = (const float*)d_in[11];
    float* out = (float*)d_out;

    cudaFuncSetAttribute(rnn_layer_kernel,
                         cudaFuncAttributeMaxDynamicSharedMemorySize, RNN_SMEM);

    float* xw;  cudaGetSymbolAddress((void**)&xw,  g_xw);
    float* y0;  cudaGetSymbolAddress((void**)&y0,  g_y0);
    float* y1;  cudaGetSymbolAddress((void**)&y1,  g_y1);

    dim3 blk(256);

    // 1) layer-0 input projection: xw = x @ w_ih0^T + b_ih0 + b_hh0
    {
        dim3 grid(HH/128, RR/128);
        gemm_bias_kernel<<<grid, blk>>>(x, w_ih0, b_ih0, b_hh0, xw, RR, HH, CC);
    }
    // 2) layer-0 recurrence
    rnn_layer_kernel<<<NB_RNN, blk, RNN_SMEM>>>(xw, h0, w_hh0, y0, TT);
    // 3) layer-1 input projection
    {
        dim3 grid(HH/128, RR/128);
        gemm_bias_kernel<<<grid, blk>>>(y0, w_ih1, b_ih1, b_hh1, xw, RR, HH, HH);
    }
    // 4) layer-1 recurrence
    rnn_layer_kernel<<<NB_RNN, blk, RNN_SMEM>>>(xw, h0 + BB*HH, w_hh1, y1, TT);
    // 5) decoder
    {
        dim3 grid(CC/128, RR/128);
        gemm_bias_kernel<<<grid, blk>>>(y1, w_dec, b_dec, nullptr, out, RR, CC, HH);
    }
    // 6) hidden states appended after decoded
    gather_hidden_kernel<<<(2*BB*HH)/256, blk>>>(out + (size_t)TT*BB*CC);
}

// round 6
// speedup vs baseline: 1.1210x; 1.1210x over previous
#include <cuda_runtime.h>
#include <math.h>

#define TT 512
#define BB 64
#define CC 256
#define HH 1024
#define RR (TT*BB)

#define WPAD 36
#define HPAD 20
#define NB_RNN 128
#define RNN_SMEM (1024*WPAD*4 + 1024*HPAD*4)   // 147456 + 81920 = 229376 B

typedef unsigned long long ull;

// ---------------- packed fp32x2 helpers ----------------
#define PACKDUP(d, s) asm("mov.b64 %0, {%1, %1};" : "=l"(d) : "r"(__float_as_uint(s)))
#define FFMA2(acc, a, b) asm("fma.rn.f32x2 %0, %1, %2, %0;" : "+l"(acc) : "l"(a), "l"(b))
#define ADD2(d, a, b) asm("add.rn.f32x2 %0, %1, %2;" : "=l"(d) : "l"(a), "l"(b))
#define UNPACK2(lo, hi, v) asm("mov.b64 {%0, %1}, %2;" : "=r"(lo), "=r"(hi) : "l"(v))

// ---------------- scratch ----------------
__device__ float g_xw[(size_t)TT*BB*HH];
__device__ float g_y0[(size_t)TT*BB*HH];
__device__ float g_y1[(size_t)TT*BB*HH];

// -------- per-batch-group grid barrier (monotonic, 4 domains of 32 CTAs) ---
__device__ unsigned g_cnt4[4*64];   // stride 64 uints = 256 B apart
__device__ unsigned g_gen4[4*64];

__device__ __forceinline__ unsigned ld_relaxed(const unsigned* p) {
    unsigned v;
    asm volatile("ld.relaxed.gpu.global.u32 %0, [%1];" : "=r"(v) : "l"(p) : "memory");
    return v;
}

__device__ __forceinline__ void group_sync(unsigned* cnt, unsigned* gen,
                                           unsigned target) {
    __syncthreads();
    if (threadIdx.x == 0) {
        unsigned old;
        asm volatile("atom.acq_rel.gpu.global.add.u32 %0, [%1], 1;"
                     : "=r"(old) : "l"(cnt) : "memory");
        if (old + 1u == 32u * target) {
            asm volatile("st.release.gpu.global.u32 [%0], %1;"
                         :: "l"(gen), "r"(target) : "memory");
        }
        unsigned v;
        do {
            asm volatile("ld.acquire.gpu.global.u32 %0, [%1];"
                         : "=r"(v) : "l"(gen) : "memory");
        } while ((int)(v - target) < 0);
    }
    __syncthreads();
}

// ---------------- parallel GEMM: out[R,N] = A[R,K] @ W[N,K]^T + b1(+b2) ----
__global__ __launch_bounds__(256) void gemm_bias_kernel(
    const float* __restrict__ A, const float* __restrict__ W,
    const float* __restrict__ b1, const float* __restrict__ b2,
    float* __restrict__ out, int R, int N, int K)
{
    __shared__ float As[16][132];
    __shared__ float Ws[16][132];
    const int tid  = threadIdx.x;
    const int r0   = blockIdx.y * 128;
    const int c0   = blockIdx.x * 128;
    const int lr   = tid >> 1;
    const int lq   = (tid & 1) * 4;
    const int lane = tid & 31;
    const int w    = tid >> 5;
    const int tx = ((w & 1) << 3) + (lane & 7);
    const int ty = ((w >> 1) << 2) + (lane >> 3);

    ull acc2[8][4];
    #pragma unroll
    for (int i = 0; i < 8; i++)
        #pragma unroll
        for (int c = 0; c < 4; c++) acc2[i][c] = 0ull;

    const float* Arow = A + (size_t)(r0 + lr) * K;
    const float* Wrow = W + (size_t)(c0 + lr) * K;

    for (int k0 = 0; k0 < K; k0 += 16) {
        #pragma unroll
        for (int l = 0; l < 2; l++) {
            float4 av = *(const float4*)(Arow + k0 + l*8 + lq);
            float4 wv = *(const float4*)(Wrow + k0 + l*8 + lq);
            int kk = l*8 + lq;
            As[kk+0][lr] = av.x;  As[kk+1][lr] = av.y;
            As[kk+2][lr] = av.z;  As[kk+3][lr] = av.w;
            Ws[kk+0][lr] = wv.x;  Ws[kk+1][lr] = wv.y;
            Ws[kk+2][lr] = wv.z;  Ws[kk+3][lr] = wv.w;
        }
        __syncthreads();
        #pragma unroll
        for (int kk = 0; kk < 16; kk++) {
            float4 a0 = *(const float4*)&As[kk][ty*8];
            float4 a1 = *(const float4*)&As[kk][ty*8+4];
            ulonglong2 wv0 = *(const ulonglong2*)&Ws[kk][tx*8];
            ulonglong2 wv1 = *(const ulonglong2*)&Ws[kk][tx*8+4];
            ull wp0 = wv0.x, wp1 = wv0.y, wp2 = wv1.x, wp3 = wv1.y;
            float av8[8] = {a0.x,a0.y,a0.z,a0.w,a1.x,a1.y,a1.z,a1.w};
            #pragma unroll
            for (int i = 0; i < 8; i++) {
                ull ad; PACKDUP(ad, av8[i]);
                FFMA2(acc2[i][0], ad, wp0);
                FFMA2(acc2[i][1], ad, wp1);
                FFMA2(acc2[i][2], ad, wp2);
                FFMA2(acc2[i][3], ad, wp3);
            }
        }
        __syncthreads();
    }

    float bias[8];
    #pragma unroll
    for (int j = 0; j < 8; j++) {
        int col = c0 + tx*8 + j;
        bias[j] = b1[col] + (b2 ? b2[col] : 0.f);
    }
    #pragma unroll
    for (int i = 0; i < 8; i++) {
        float o[8];
        #pragma unroll
        for (int c = 0; c < 4; c++) {
            unsigned lo, hi;
            UNPACK2(lo, hi, acc2[i][c]);
            o[2*c]   = __uint_as_float(lo) + bias[2*c];
            o[2*c+1] = __uint_as_float(hi) + bias[2*c+1];
        }
        int row = r0 + ty*8 + i;
        *(float4*)(out + (size_t)row*N + c0 + tx*8)     = make_float4(o[0],o[1],o[2],o[3]);
        *(float4*)(out + (size_t)row*N + c0 + tx*8 + 4) = make_float4(o[4],o[5],o[6],o[7]);
    }
}

// ------------- persistent recurrence: y[t]=tanh(xw[t]+h_{t-1}@Whh^T) -------
// 128 CTAs = 4 batch-groups(16) x 32 col-groups(32). 512 thr = 16 warps.
// Warp w owns tile (4 batch x 8 cols); lanes = 32-way K split; shuffle reduce.
__global__ __launch_bounds__(512) void rnn_layer_kernel(
    const float* __restrict__ xw, const float* __restrict__ h0,
    const float* __restrict__ Whh, float* __restrict__ y, int nsteps)
{
    extern __shared__ float smem[];
    float* Wsh = smem;                 // [1024][WPAD] transposed W slice
    float* hsm = smem + 1024*WPAD;     // [1024][HPAD] transposed h

    const int tid = threadIdx.x;
    const int bid = blockIdx.x;
    const int cg  = bid & 31;
    const int bg  = bid >> 5;
    const int c0  = cg * 32;

    unsigned* cnt = &g_cnt4[bg*64];
    unsigned* gen = &g_gen4[bg*64];
    unsigned gen0 = ld_relaxed(gen);   // safe: group's gen frozen until we arrive

    // one-time W slice load, transposed: Wsh[k][j_local]
    {
        const int j  = tid & 31;
        const int kc = tid >> 5;       // 0..15, each 64 k
        const float* wr = Whh + (size_t)(c0 + j) * HH + kc*64;
        #pragma unroll
        for (int i = 0; i < 16; i++) {
            float4 v = *(const float4*)(wr + i*4);
            int k = kc*64 + i*4;
            Wsh[(k+0)*WPAD + j] = v.x;
            Wsh[(k+1)*WPAD + j] = v.y;
            Wsh[(k+2)*WPAD + j] = v.z;
            Wsh[(k+3)*WPAD + j] = v.w;
        }
    }
    __syncthreads();   // W ready

    const int hb   = tid & 15;         // h-store: batch lane
    const int hkc  = tid >> 4;         // h-store: 32 chunks of 32 k
    const int warp = tid >> 5;
    const int lane = tid & 31;
    const int bl0  = (warp >> 2) * 4;  // 0,4,8,12
    const int jl0  = (warp & 3) * 8;   // 0,8,16,24
    // epilogue: even lanes write pair p = (lane>>1)&15 of this warp's tile
    const int p    = (lane >> 1) & 15;
    const int eb   = bl0 + (p >> 2);
    const int ej   = jl0 + (p & 3) * 2;

    for (int t = 0; t < nsteps; t++) {
        const float* hprev = (t == 0) ? h0 : (y + (size_t)(t-1)*BB*HH);

        // prefetch epilogue operand (depends only on t)
        size_t oidx = ((size_t)t*BB + bg*16 + eb)*HH + c0 + ej;
        float2 xwv = *(const float2*)&xw[oidx];

        // stage h tile transposed: hsm[k][b_local]
        {
            const float* hr = hprev + (size_t)(bg*16 + hb)*HH + hkc*32;
            #pragma unroll
            for (int i = 0; i < 8; i++) {
                float4 v = *(const float4*)(hr + i*4);
                int k = hkc*32 + i*4;
                hsm[(k+0)*HPAD + hb] = v.x;
                hsm[(k+1)*HPAD + hb] = v.y;
                hsm[(k+2)*HPAD + hb] = v.z;
                hsm[(k+3)*HPAD + hb] = v.w;
            }
        }
        __syncthreads();

        ull v[16];   // acc, flat idx = r*4 + c  (r=batch, c=col-pair)
        #pragma unroll
        for (int i = 0; i < 16; i++) v[i] = 0ull;

        #pragma unroll 4
        for (int i = 0; i < 32; i++) {
            int k = i*32 + lane;
            float4 hv = *(const float4*)&hsm[k*HPAD + bl0];
            ulonglong2 wv0 = *(const ulonglong2*)&Wsh[k*WPAD + jl0];
            ulonglong2 wv1 = *(const ulonglong2*)&Wsh[k*WPAD + jl0 + 4];
            ull wp0 = wv0.x, wp1 = wv0.y, wp2 = wv1.x, wp3 = wv1.y;
            float hr4[4] = {hv.x, hv.y, hv.z, hv.w};
            #pragma unroll
            for (int r = 0; r < 4; r++) {
                ull hd; PACKDUP(hd, hr4[r]);
                FFMA2(v[r*4+0], hd, wp0);
                FFMA2(v[r*4+1], hd, wp1);
                FFMA2(v[r*4+2], hd, wp2);
                FFMA2(v[r*4+3], hd, wp3);
            }
        }

        // in-warp butterfly reduce: 16 values x 32 lanes -> lane pair holds v[p]
        #pragma unroll
        for (int si = 0; si < 4; si++) {
            const int s  = 16 >> si;       // 16,8,4,2
            const int nv = 8 >> si;        // 8,4,2,1 values exchanged
            const bool up = lane & s;
            #pragma unroll
            for (int i = 0; i < nv; i++) {
                ull give = up ? v[i] : v[i + nv];
                ull got  = __shfl_xor_sync(0xFFFFFFFFu, give, s);
                ull keep = up ? v[i + nv] : v[i];
                ADD2(v[i], keep, got);
            }
        }
        {   // final: merge lane pairs (sum over all 32 lanes)
            ull got = __shfl_xor_sync(0xFFFFFFFFu, v[0], 1);
            ADD2(v[0], v[0], got);
        }

        if (!(lane & 1)) {
            unsigned lo, hi;
            UNPACK2(lo, hi, v[0]);
            float2 rv;
            rv.x = tanhf(xwv.x + __uint_as_float(lo));
            rv.y = tanhf(xwv.y + __uint_as_float(hi));
            *(float2*)&y[oidx] = rv;
        }

        group_sync(cnt, gen, gen0 + (unsigned)t + 1u);
    }
}

// ------------- hidden-state gather ----------------
__global__ void gather_hidden_kernel(float* __restrict__ out_hidden)
{
    int i = blockIdx.x * blockDim.x + threadIdx.x;
    const float* src = (i < BB*HH)
        ? (g_y0 + (size_t)(TT-1)*BB*HH + i)
        : (g_y1 + (size_t)(TT-1)*BB*HH + (i - BB*HH));
    out_hidden[i] = *src;
}

extern "C" void kernel_launch(void* const* d_in, const int* in_sizes, int n_in,
                              void* d_out, int out_size) {
    const float* x     = (const float*)d_in[0];
    const float* h0    = (const float*)d_in[1];
    const float* w_ih0 = (const float*)d_in[2];
    const float* w_hh0 = (const float*)d_in[3];
    const float* b_ih0 = (const float*)d_in[4];
    const float* b_hh0 = (const float*)d_in[5];
    const float* w_ih1 = (const float*)d_in[6];
    const float* w_hh1 = (const float*)d_in[7];
    const float* b_ih1 = (const float*)d_in[8];
    const float* b_hh1 = (const float*)d_in[9];
    const float* w_dec = (const float*)d_in[10];
    const float* b_dec = (const float*)d_in[11];
    float* out = (float*)d_out;

    cudaFuncSetAttribute(rnn_layer_kernel,
                         cudaFuncAttributeMaxDynamicSharedMemorySize, RNN_SMEM);

    float* xw;  cudaGetSymbolAddress((void**)&xw,  g_xw);
    float* y0;  cudaGetSymbolAddress((void**)&y0,  g_y0);
    float* y1;  cudaGetSymbolAddress((void**)&y1,  g_y1);

    // 1) layer-0 input projection: xw = x @ w_ih0^T + b_ih0 + b_hh0
    {
        dim3 grid(HH/128, RR/128);
        gemm_bias_kernel<<<grid, 256>>>(x, w_ih0, b_ih0, b_hh0, xw, RR, HH, CC);
    }
    // 2) layer-0 recurrence
    rnn_layer_kernel<<<NB_RNN, 512, RNN_SMEM>>>(xw, h0, w_hh0, y0, TT);
    // 3) layer-1 input projection
    {
        dim3 grid(HH/128, RR/128);
        gemm_bias_kernel<<<grid, 256>>>(y0, w_ih1, b_ih1, b_hh1, xw, RR, HH, HH);
    }
    // 4) layer-1 recurrence
    rnn_layer_kernel<<<NB_RNN, 512, RNN_SMEM>>>(xw, h0 + BB*HH, w_hh1, y1, TT);
    // 5) decoder
    {
        dim3 grid(CC/128, RR/128);
        gemm_bias_kernel<<<grid, 256>>>(y1, w_dec, b_dec, nullptr, out, RR, CC, HH);
    }
    // 6) hidden states appended after decoded
    gather_hidden_kernel<<<(2*BB*HH)/256, 256>>>(out + (size_t)TT*BB*CC);
}

// round 8
// speedup vs baseline: 1.1455x; 1.0218x over previous
#include <cuda_runtime.h>
#include <math.h>

#define TT 512
#define BB 64
#define CC 256
#define HH 1024
#define RR (TT*BB)

#define WPAD 36
#define HPAD 20
#define NB_RNN 128
// W 1024x36 f + h 1024x20 f + sred 8*32 ull
#define RNN_SMEM (1024*WPAD*4 + 1024*HPAD*4 + 8*32*8)   // 231424 B

typedef unsigned long long ull;

// ---------------- packed fp32x2 helpers ----------------
#define PACKDUP(d, s) asm("mov.b64 %0, {%1, %1};" : "=l"(d) : "r"(__float_as_uint(s)))
#define FFMA2(acc, a, b) asm("fma.rn.f32x2 %0, %1, %2, %0;" : "+l"(acc) : "l"(a), "l"(b))
#define ADD2(d, a, b) asm("add.rn.f32x2 %0, %1, %2;" : "=l"(d) : "l"(a), "l"(b))
#define UNPACK2(lo, hi, v) asm("mov.b64 {%0, %1}, %2;" : "=r"(lo), "=r"(hi) : "l"(v))

// ---------------- scratch ----------------
__device__ float g_xw[(size_t)TT*BB*HH];
__device__ float g_y0[(size_t)TT*BB*HH];
__device__ float g_y1[(size_t)TT*BB*HH];

// -------- per-batch-group grid barrier (monotonic, 4 domains of 32 CTAs) ---
__device__ unsigned g_cnt4[4*64];
__device__ unsigned g_gen4[4*64];

__device__ __forceinline__ unsigned ld_relaxed(const unsigned* p) {
    unsigned v;
    asm volatile("ld.relaxed.gpu.global.u32 %0, [%1];" : "=r"(v) : "l"(p) : "memory");
    return v;
}

__device__ __forceinline__ void group_sync(unsigned* cnt, unsigned* gen,
                                           unsigned target) {
    __syncthreads();
    if (threadIdx.x == 0) {
        unsigned old;
        asm volatile("atom.acq_rel.gpu.global.add.u32 %0, [%1], 1;"
                     : "=r"(old) : "l"(cnt) : "memory");
        if (old + 1u == 32u * target) {
            asm volatile("st.release.gpu.global.u32 [%0], %1;"
                         :: "l"(gen), "r"(target) : "memory");
        }
        unsigned v;
        do {
            asm volatile("ld.acquire.gpu.global.u32 %0, [%1];"
                         : "=r"(v) : "l"(gen) : "memory");
        } while ((int)(v - target) < 0);
    }
    __syncthreads();
}

// ---------------- parallel GEMM: out[R,N] = A[R,K] @ W[N,K]^T + b1(+b2) ----
__global__ __launch_bounds__(256) void gemm_bias_kernel(
    const float* __restrict__ A, const float* __restrict__ W,
    const float* __restrict__ b1, const float* __restrict__ b2,
    float* __restrict__ out, int R, int N, int K)
{
    __shared__ float As[16][132];
    __shared__ float Ws[16][132];
    const int tid  = threadIdx.x;
    const int r0   = blockIdx.y * 128;
    const int c0   = blockIdx.x * 128;
    const int lr   = tid >> 1;
    const int lq   = (tid & 1) * 4;
    const int lane = tid & 31;
    const int w    = tid >> 5;
    const int tx = ((w & 1) << 3) + (lane & 7);
    const int ty = ((w >> 1) << 2) + (lane >> 3);

    ull acc2[8][4];
    #pragma unroll
    for (int i = 0; i < 8; i++)
        #pragma unroll
        for (int c = 0; c < 4; c++) acc2[i][c] = 0ull;

    const float* Arow = A + (size_t)(r0 + lr) * K;
    const float* Wrow = W + (size_t)(c0 + lr) * K;

    for (int k0 = 0; k0 < K; k0 += 16) {
        #pragma unroll
        for (int l = 0; l < 2; l++) {
            float4 av = *(const float4*)(Arow + k0 + l*8 + lq);
            float4 wv = *(const float4*)(Wrow + k0 + l*8 + lq);
            int kk = l*8 + lq;
            As[kk+0][lr] = av.x;  As[kk+1][lr] = av.y;
            As[kk+2][lr] = av.z;  As[kk+3][lr] = av.w;
            Ws[kk+0][lr] = wv.x;  Ws[kk+1][lr] = wv.y;
            Ws[kk+2][lr] = wv.z;  Ws[kk+3][lr] = wv.w;
        }
        __syncthreads();
        #pragma unroll
        for (int kk = 0; kk < 16; kk++) {
            float4 a0 = *(const float4*)&As[kk][ty*8];
            float4 a1 = *(const float4*)&As[kk][ty*8+4];
            ulonglong2 wv0 = *(const ulonglong2*)&Ws[kk][tx*8];
            ulonglong2 wv1 = *(const ulonglong2*)&Ws[kk][tx*8+4];
            ull wp0 = wv0.x, wp1 = wv0.y, wp2 = wv1.x, wp3 = wv1.y;
            float av8[8] = {a0.x,a0.y,a0.z,a0.w,a1.x,a1.y,a1.z,a1.w};
            #pragma unroll
            for (int i = 0; i < 8; i++) {
                ull ad; PACKDUP(ad, av8[i]);
                FFMA2(acc2[i][0], ad, wp0);
                FFMA2(acc2[i][1], ad, wp1);
                FFMA2(acc2[i][2], ad, wp2);
                FFMA2(acc2[i][3], ad, wp3);
            }
        }
        __syncthreads();
    }

    float bias[8];
    #pragma unroll
    for (int j = 0; j < 8; j++) {
        int col = c0 + tx*8 + j;
        bias[j] = b1[col] + (b2 ? b2[col] : 0.f);
    }
    #pragma unroll
    for (int i = 0; i < 8; i++) {
        float o[8];
        #pragma unroll
        for (int c = 0; c < 4; c++) {
            unsigned lo, hi;
            UNPACK2(lo, hi, acc2[i][c]);
            o[2*c]   = __uint_as_float(lo) + bias[2*c];
            o[2*c+1] = __uint_as_float(hi) + bias[2*c+1];
        }
        int row = r0 + ty*8 + i;
        *(float4*)(out + (size_t)row*N + c0 + tx*8)     = make_float4(o[0],o[1],o[2],o[3]);
        *(float4*)(out + (size_t)row*N + c0 + tx*8 + 4) = make_float4(o[4],o[5],o[6],o[7]);
    }
}

// ------------- persistent recurrence: y[t]=tanh(xw[t]+h_{t-1}@Whh^T) -------
// 128 CTAs = 4 batch-groups(16b) x 32 col-groups(32j). 512 thr = 16 warps.
// Warps w and w+8 co-own tile (w&7) = 8b x 8j; halves split k 64-ways.
// Full 5-stage butterfly -> lane l holds pair p=l; smem merge of halves.
__global__ __launch_bounds__(512) void rnn_layer_kernel(
    const float* __restrict__ xw, const float* __restrict__ h0,
    const float* __restrict__ Whh, float* __restrict__ y, int nsteps)
{
    extern __shared__ float smem[];
    float* Wsh = smem;                           // [1024][WPAD]
    float* hsm = smem + 1024*WPAD;               // [1024][HPAD]
    ull*   sred = (ull*)(smem + 1024*WPAD + 1024*HPAD);  // [8 tiles][32]

    const int tid = threadIdx.x;
    const int bid = blockIdx.x;
    const int cg  = bid & 31;
    const int bg  = bid >> 5;
    const int c0  = cg * 32;

    unsigned* cnt = &g_cnt4[bg*64];
    unsigned* gen = &g_gen4[bg*64];
    unsigned gen0 = ld_relaxed(gen);

    // one-time W slice load, transposed: Wsh[k][j_local]
    {
        const int j  = tid & 31;
        const int kc = tid >> 5;       // 0..15, each 64 k
        const float* wr = Whh + (size_t)(c0 + j) * HH + kc*64;
        #pragma unroll
        for (int i = 0; i < 16; i++) {
            float4 v = *(const float4*)(wr + i*4);
            int k = kc*64 + i*4;
            Wsh[(k+0)*WPAD + j] = v.x;
            Wsh[(k+1)*WPAD + j] = v.y;
            Wsh[(k+2)*WPAD + j] = v.z;
            Wsh[(k+3)*WPAD + j] = v.w;
        }
    }
    __syncthreads();

    // staging mapping (identical to proven r6)
    const int sb   = tid & 15;
    const int hkc  = tid >> 4;         // 0..31, each 32 k
    // compute mapping
    const int warp = tid >> 5;
    const int lane = tid & 31;
    const int half = warp >> 3;        // k-half
    const int wt   = warp & 7;         // tile id
    const int bl0  = (wt >> 2) * 8;    // 0 or 8
    const int jl0  = (wt & 3) * 8;     // 0,8,16,24
    const int kbase = half * 512;
    // epilogue mapping: lane l holds pair p=l of tile wt
    const int eb   = bl0 + (lane >> 2);
    const int ej   = jl0 + (lane & 3) * 2;

    for (int t = 0; t < nsteps; t++) {
        const float* hprev = (t == 0) ? h0 : (y + (size_t)(t-1)*BB*HH);

        // prefetch epilogue operand (used by half 0 only; harmless for half 1)
        size_t oidx = ((size_t)t*BB + bg*16 + eb)*HH + c0 + ej;
        float2 xwv = *(const float2*)&xw[oidx];

        // stage h tile transposed: hsm[k][b_local]
        {
            const float* hr = hprev + (size_t)(bg*16 + sb)*HH + hkc*32;
            #pragma unroll
            for (int i = 0; i < 8; i++) {
                float4 v = *(const float4*)(hr + i*4);
                int k = hkc*32 + i*4;
                hsm[(k+0)*HPAD + sb] = v.x;
                hsm[(k+1)*HPAD + sb] = v.y;
                hsm[(k+2)*HPAD + sb] = v.z;
                hsm[(k+3)*HPAD + sb] = v.w;
            }
        }
        __syncthreads();

        ull v[32];   // flat idx = r*4 + c  (r=batch 0..7, c=col-pair 0..3)
        #pragma unroll
        for (int i = 0; i < 32; i++) v[i] = 0ull;

        #pragma unroll 2
        for (int i = 0; i < 16; i++) {
            int k = kbase + i*32 + lane;
            float4 hv0 = *(const float4*)&hsm[k*HPAD + bl0];
            float4 hv1 = *(const float4*)&hsm[k*HPAD + bl0 + 4];
            ulonglong2 wv0 = *(const ulonglong2*)&Wsh[k*WPAD + jl0];
            ulonglong2 wv1 = *(const ulonglong2*)&Wsh[k*WPAD + jl0 + 4];
            ull wp0 = wv0.x, wp1 = wv0.y, wp2 = wv1.x, wp3 = wv1.y;
            float hr8[8] = {hv0.x,hv0.y,hv0.z,hv0.w,hv1.x,hv1.y,hv1.z,hv1.w};
            #pragma unroll
            for (int r = 0; r < 8; r++) {
                ull hd; PACKDUP(hd, hr8[r]);
                FFMA2(v[r*4+0], hd, wp0);
                FFMA2(v[r*4+1], hd, wp1);
                FFMA2(v[r*4+2], hd, wp2);
                FFMA2(v[r*4+3], hd, wp3);
            }
        }

        // 5-stage in-warp butterfly: lane l ends holding full sum of pair p=l
        #pragma unroll
        for (int si = 0; si < 5; si++) {
            const int s  = 16 >> si;       // 16,8,4,2,1
            const int nv = 16 >> si;       // values exchanged
            const bool up = lane & s;
            #pragma unroll
            for (int i = 0; i < nv; i++) {
                ull give = up ? v[i] : v[i + nv];
                ull got  = __shfl_xor_sync(0xFFFFFFFFu, give, s);
                ull keep = up ? v[i + nv] : v[i];
                ADD2(v[i], keep, got);
            }
        }

        // merge k-halves: half 1 writes partial, half 0 adds + epilogue
        if (half) sred[wt*32 + lane] = v[0];
        __syncthreads();
        if (!half) {
            ADD2(v[0], v[0], sred[wt*32 + lane]);
            unsigned lo, hi;
            UNPACK2(lo, hi, v[0]);
            float2 rv;
            rv.x = tanhf(xwv.x + __uint_as_float(lo));
            rv.y = tanhf(xwv.y + __uint_as_float(hi));
            *(float2*)&y[oidx] = rv;
        }

        group_sync(cnt, gen, gen0 + (unsigned)t + 1u);
    }
}

// ------------- hidden-state gather ----------------
__global__ void gather_hidden_kernel(float* __restrict__ out_hidden)
{
    int i = blockIdx.x * blockDim.x + threadIdx.x;
    const float* src = (i < BB*HH)
        ? (g_y0 + (size_t)(TT-1)*BB*HH + i)
        : (g_y1 + (size_t)(TT-1)*BB*HH + (i - BB*HH));
    out_hidden[i] = *src;
}

extern "C" void kernel_launch(void* const* d_in, const int* in_sizes, int n_in,
                              void* d_out, int out_size) {
    const float* x     = (const float*)d_in[0];
    const float* h0    = (const float*)d_in[1];
    const float* w_ih0 = (const float*)d_in[2];
    const float* w_hh0 = (const float*)d_in[3];
    const float* b_ih0 = (const float*)d_in[4];
    const float* b_hh0 = (const float*)d_in[5];
    const float* w_ih1 = (const float*)d_in[6];
    const float* w_hh1 = (const float*)d_in[7];
    const float* b_ih1 = (const float*)d_in[8];
    const float* b_hh1 = (const float*)d_in[9];
    const float* w_dec = (const float*)d_in[10];
    const float* b_dec = (const float*)d_in[11];
    float* out = (float*)d_out;

    cudaFuncSetAttribute(rnn_layer_kernel,
                         cudaFuncAttributeMaxDynamicSharedMemorySize, RNN_SMEM);

    float* xw;  cudaGetSymbolAddress((void**)&xw,  g_xw);
    float* y0;  cudaGetSymbolAddress((void**)&y0,  g_y0);
    float* y1;  cudaGetSymbolAddress((void**)&y1,  g_y1);

    // 1) layer-0 input projection: xw = x @ w_ih0^T + b_ih0 + b_hh0
    {
        dim3 grid(HH/128, RR/128);
        gemm_bias_kernel<<<grid, 256>>>(x, w_ih0, b_ih0, b_hh0, xw, RR, HH, CC);
    }
    // 2) layer-0 recurrence
    rnn_layer_kernel<<<NB_RNN, 512, RNN_SMEM>>>(xw, h0, w_hh0, y0, TT);
    // 3) layer-1 input projection
    {
        dim3 grid(HH/128, RR/128);
        gemm_bias_kernel<<<grid, 256>>>(y0, w_ih1, b_ih1, b_hh1, xw, RR, HH, HH);
    }
    // 4) layer-1 recurrence
    rnn_layer_kernel<<<NB_RNN, 512, RNN_SMEM>>>(xw, h0 + BB*HH, w_hh1, y1, TT);
    // 5) decoder
    {
        dim3 grid(CC/128, RR/128);
        gemm_bias_kernel<<<grid, 256>>>(y1, w_dec, b_dec, nullptr, out, RR, CC, HH);
    }
    // 6) hidden states appended after decoded
    gather_hidden_kernel<<<(2*BB*HH)/256, 256>>>(out + (size_t)TT*BB*CC);
}

// round 9
// speedup vs baseline: 1.1535x; 1.0070x over previous
#include <cuda_runtime.h>
#include <math.h>

#define TT 512
#define BB 64
#define CC 256
#define HH 1024
#define RR (TT*BB)

#define WPAD 36
#define HPAD 20
#define NB_RNN 128
// W 1024x36 f + h 1024x20 f + sred 16 tiles x 16 pairs (ull)
#define RNN_SMEM (1024*WPAD*4 + 1024*HPAD*4 + 16*16*8)   // 231424 B

typedef unsigned long long ull;

// ---------------- packed fp32x2 helpers ----------------
#define PACKDUP(d, s) asm("mov.b64 %0, {%1, %1};" : "=l"(d) : "r"(__float_as_uint(s)))
#define FFMA2(acc, a, b) asm("fma.rn.f32x2 %0, %1, %2, %0;" : "+l"(acc) : "l"(a), "l"(b))
#define ADD2(d, a, b) asm("add.rn.f32x2 %0, %1, %2;" : "=l"(d) : "l"(a), "l"(b))
#define UNPACK2(lo, hi, v) asm("mov.b64 {%0, %1}, %2;" : "=r"(lo), "=r"(hi) : "l"(v))

// ---------------- scratch ----------------
__device__ float g_xw[(size_t)TT*BB*HH];
__device__ float g_y0[(size_t)TT*BB*HH];
__device__ float g_y1[(size_t)TT*BB*HH];

// -------- per-batch-group grid barrier (monotonic, 4 domains of 32 CTAs) ---
__device__ unsigned g_cnt4[4*64];
__device__ unsigned g_gen4[4*64];

__device__ __forceinline__ unsigned ld_relaxed(const unsigned* p) {
    unsigned v;
    asm volatile("ld.relaxed.gpu.global.u32 %0, [%1];" : "=r"(v) : "l"(p) : "memory");
    return v;
}

__device__ __forceinline__ void group_sync(unsigned* cnt, unsigned* gen,
                                           unsigned target) {
    __syncthreads();
    if (threadIdx.x == 0) {
        unsigned old;
        asm volatile("atom.acq_rel.gpu.global.add.u32 %0, [%1], 1;"
                     : "=r"(old) : "l"(cnt) : "memory");
        if (old + 1u == 32u * target) {
            asm volatile("st.release.gpu.global.u32 [%0], %1;"
                         :: "l"(gen), "r"(target) : "memory");
        }
        unsigned v;
        do {
            asm volatile("ld.acquire.gpu.global.u32 %0, [%1];"
                         : "=r"(v) : "l"(gen) : "memory");
        } while ((int)(v - target) < 0);
    }
    __syncthreads();
}

// ---------------- parallel GEMM: out[R,N] = A[R,K] @ W[N,K]^T + b1(+b2) ----
__global__ __launch_bounds__(256) void gemm_bias_kernel(
    const float* __restrict__ A, const float* __restrict__ W,
    const float* __restrict__ b1, const float* __restrict__ b2,
    float* __restrict__ out, int R, int N, int K)
{
    __shared__ float As[16][132];
    __shared__ float Ws[16][132];
    const int tid  = threadIdx.x;
    const int r0   = blockIdx.y * 128;
    const int c0   = blockIdx.x * 128;
    const int lr   = tid >> 1;
    const int lq   = (tid & 1) * 4;
    const int lane = tid & 31;
    const int w    = tid >> 5;
    const int tx = ((w & 1) << 3) + (lane & 7);
    const int ty = ((w >> 1) << 2) + (lane >> 3);

    ull acc2[8][4];
    #pragma unroll
    for (int i = 0; i < 8; i++)
        #pragma unroll
        for (int c = 0; c < 4; c++) acc2[i][c] = 0ull;

    const float* Arow = A + (size_t)(r0 + lr) * K;
    const float* Wrow = W + (size_t)(c0 + lr) * K;

    for (int k0 = 0; k0 < K; k0 += 16) {
        #pragma unroll
        for (int l = 0; l < 2; l++) {
            float4 av = *(const float4*)(Arow + k0 + l*8 + lq);
            float4 wv = *(const float4*)(Wrow + k0 + l*8 + lq);
            int kk = l*8 + lq;
            As[kk+0][lr] = av.x;  As[kk+1][lr] = av.y;
            As[kk+2][lr] = av.z;  As[kk+3][lr] = av.w;
            Ws[kk+0][lr] = wv.x;  Ws[kk+1][lr] = wv.y;
            Ws[kk+2][lr] = wv.z;  Ws[kk+3][lr] = wv.w;
        }
        __syncthreads();
        #pragma unroll
        for (int kk = 0; kk < 16; kk++) {
            float4 a0 = *(const float4*)&As[kk][ty*8];
            float4 a1 = *(const float4*)&As[kk][ty*8+4];
            ulonglong2 wv0 = *(const ulonglong2*)&Ws[kk][tx*8];
            ulonglong2 wv1 = *(const ulonglong2*)&Ws[kk][tx*8+4];
            ull wp0 = wv0.x, wp1 = wv0.y, wp2 = wv1.x, wp3 = wv1.y;
            float av8[8] = {a0.x,a0.y,a0.z,a0.w,a1.x,a1.y,a1.z,a1.w};
            #pragma unroll
            for (int i = 0; i < 8; i++) {
                ull ad; PACKDUP(ad, av8[i]);
                FFMA2(acc2[i][0], ad, wp0);
                FFMA2(acc2[i][1], ad, wp1);
                FFMA2(acc2[i][2], ad, wp2);
                FFMA2(acc2[i][3], ad, wp3);
            }
        }
        __syncthreads();
    }

    float bias[8];
    #pragma unroll
    for (int j = 0; j < 8; j++) {
        int col = c0 + tx*8 + j;
        bias[j] = b1[col] + (b2 ? b2[col] : 0.f);
    }
    #pragma unroll
    for (int i = 0; i < 8; i++) {
        float o[8];
        #pragma unroll
        for (int c = 0; c < 4; c++) {
            unsigned lo, hi;
            UNPACK2(lo, hi, acc2[i][c]);
            o[2*c]   = __uint_as_float(lo) + bias[2*c];
            o[2*c+1] = __uint_as_float(hi) + bias[2*c+1];
        }
        int row = r0 + ty*8 + i;
        *(float4*)(out + (size_t)row*N + c0 + tx*8)     = make_float4(o[0],o[1],o[2],o[3]);
        *(float4*)(out + (size_t)row*N + c0 + tx*8 + 4) = make_float4(o[4],o[5],o[6],o[7]);
    }
}

// ------------- persistent recurrence: y[t]=tanh(xw[t]+h_{t-1}@Whh^T) -------
// 128 CTAs = 4 batch-groups(16b) x 32 col-groups(32j). 1024 thr = 32 warps.
// Warp w: half = w>>4 (k 512-split), tile = w&15 (4b x 8j). r6-proven core,
// 4-stage butterfly + pair merge; r8-proven smem half-merge.
__global__ __launch_bounds__(1024) void rnn_layer_kernel(
    const float* __restrict__ xw, const float* __restrict__ h0,
    const float* __restrict__ Whh, float* __restrict__ y, int nsteps)
{
    extern __shared__ float smem[];
    float* Wsh = smem;                           // [1024][WPAD]
    float* hsm = smem + 1024*WPAD;               // [1024][HPAD]
    ull*   sred = (ull*)(smem + 1024*WPAD + 1024*HPAD);  // [16 tiles][16 pairs]

    const int tid = threadIdx.x;
    const int bid = blockIdx.x;
    const int cg  = bid & 31;
    const int bg  = bid >> 5;
    const int c0  = cg * 32;

    unsigned* cnt = &g_cnt4[bg*64];
    unsigned* gen = &g_gen4[bg*64];
    unsigned gen0 = ld_relaxed(gen);

    // one-time W slice load, transposed: Wsh[k][j_local]
    {
        const int j  = tid & 31;
        const int kc = tid >> 5;       // 0..31, each 32 k
        const float* wr = Whh + (size_t)(c0 + j) * HH + kc*32;
        #pragma unroll
        for (int i = 0; i < 8; i++) {
            float4 v = *(const float4*)(wr + i*4);
            int k = kc*32 + i*4;
            Wsh[(k+0)*WPAD + j] = v.x;
            Wsh[(k+1)*WPAD + j] = v.y;
            Wsh[(k+2)*WPAD + j] = v.z;
            Wsh[(k+3)*WPAD + j] = v.w;
        }
    }
    __syncthreads();

    // staging mapping: 1024 threads, each 16 k of one batch row
    const int sb   = tid & 15;
    const int skc  = tid >> 4;         // 0..63, each 16 k
    // compute mapping
    const int warp = tid >> 5;
    const int lane = tid & 31;
    const int half = warp >> 4;        // k-half
    const int wt   = warp & 15;        // tile id
    const int bl0  = (wt >> 2) * 4;    // 0,4,8,12
    const int jl0  = (wt & 3) * 8;     // 0,8,16,24
    const int kbase = half * 512;
    // epilogue: even lanes hold pair p = (lane>>1)&15 of tile wt
    const int p    = (lane >> 1) & 15;
    const int eb   = bl0 + (p >> 2);
    const int ej   = jl0 + (p & 3) * 2;

    for (int t = 0; t < nsteps; t++) {
        const float* hprev = (t == 0) ? h0 : (y + (size_t)(t-1)*BB*HH);

        // prefetch epilogue operand
        size_t oidx = ((size_t)t*BB + bg*16 + eb)*HH + c0 + ej;
        float2 xwv = *(const float2*)&xw[oidx];

        // stage h tile transposed: hsm[k][b_local]
        {
            const float* hr = hprev + (size_t)(bg*16 + sb)*HH + skc*16;
            #pragma unroll
            for (int i = 0; i < 4; i++) {
                float4 v = *(const float4*)(hr + i*4);
                int k = skc*16 + i*4;
                hsm[(k+0)*HPAD + sb] = v.x;
                hsm[(k+1)*HPAD + sb] = v.y;
                hsm[(k+2)*HPAD + sb] = v.z;
                hsm[(k+3)*HPAD + sb] = v.w;
            }
        }
        __syncthreads();

        ull v[16];   // flat idx = r*4 + c  (r=batch 0..3, c=col-pair 0..3)
        #pragma unroll
        for (int i = 0; i < 16; i++) v[i] = 0ull;

        #pragma unroll 4
        for (int i = 0; i < 16; i++) {
            int k = kbase + i*32 + lane;
            float4 hv = *(const float4*)&hsm[k*HPAD + bl0];
            ulonglong2 wv0 = *(const ulonglong2*)&Wsh[k*WPAD + jl0];
            ulonglong2 wv1 = *(const ulonglong2*)&Wsh[k*WPAD + jl0 + 4];
            ull wp0 = wv0.x, wp1 = wv0.y, wp2 = wv1.x, wp3 = wv1.y;
            float hr4[4] = {hv.x, hv.y, hv.z, hv.w};
            #pragma unroll
            for (int r = 0; r < 4; r++) {
                ull hd; PACKDUP(hd, hr4[r]);
                FFMA2(v[r*4+0], hd, wp0);
                FFMA2(v[r*4+1], hd, wp1);
                FFMA2(v[r*4+2], hd, wp2);
                FFMA2(v[r*4+3], hd, wp3);
            }
        }

        // 4-stage butterfly + pair merge: even lanes hold sum of pair p
        #pragma unroll
        for (int si = 0; si < 4; si++) {
            const int s  = 16 >> si;       // 16,8,4,2
            const int nv = 8 >> si;        // 8,4,2,1
            const bool up = lane & s;
            #pragma unroll
            for (int i = 0; i < nv; i++) {
                ull give = up ? v[i] : v[i + nv];
                ull got  = __shfl_xor_sync(0xFFFFFFFFu, give, s);
                ull keep = up ? v[i + nv] : v[i];
                ADD2(v[i], keep, got);
            }
        }
        {
            ull got = __shfl_xor_sync(0xFFFFFFFFu, v[0], 1);
            ADD2(v[0], v[0], got);
        }

        // merge k-halves via sred (even lanes carry valid pairs)
        if (half && !(lane & 1)) sred[wt*16 + p] = v[0];
        __syncthreads();
        if (!half && !(lane & 1)) {
            ADD2(v[0], v[0], sred[wt*16 + p]);
            unsigned lo, hi;
            UNPACK2(lo, hi, v[0]);
            float2 rv;
            rv.x = tanhf(xwv.x + __uint_as_float(lo));
            rv.y = tanhf(xwv.y + __uint_as_float(hi));
            *(float2*)&y[oidx] = rv;
        }

        group_sync(cnt, gen, gen0 + (unsigned)t + 1u);
    }
}

// ------------- hidden-state gather ----------------
__global__ void gather_hidden_kernel(float* __restrict__ out_hidden)
{
    int i = blockIdx.x * blockDim.x + threadIdx.x;
    const float* src = (i < BB*HH)
        ? (g_y0 + (size_t)(TT-1)*BB*HH + i)
        : (g_y1 + (size_t)(TT-1)*BB*HH + (i - BB*HH));
    out_hidden[i] = *src;
}

extern "C" void kernel_launch(void* const* d_in, const int* in_sizes, int n_in,
                              void* d_out, int out_size) {
    const float* x     = (const float*)d_in[0];
    const float* h0    = (const float*)d_in[1];
    const float* w_ih0 = (const float*)d_in[2];
    const float* w_hh0 = (const float*)d_in[3];
    const float* b_ih0 = (const float*)d_in[4];
    const float* b_hh0 = (const float*)d_in[5];
    const float* w_ih1 = (const float*)d_in[6];
    const float* w_hh1 = (const float*)d_in[7];
    const float* b_ih1 = (const float*)d_in[8];
    const float* b_hh1 = (const float*)d_in[9];
    const float* w_dec = (const float*)d_in[10];
    const float* b_dec = (const float*)d_in[11];
    float* out = (float*)d_out;

    cudaFuncSetAttribute(rnn_layer_kernel,
                         cudaFuncAttributeMaxDynamicSharedMemorySize, RNN_SMEM);

    float* xw;  cudaGetSymbolAddress((void**)&xw,  g_xw);
    float* y0;  cudaGetSymbolAddress((void**)&y0,  g_y0);
    float* y1;  cudaGetSymbolAddress((void**)&y1,  g_y1);

    // 1) layer-0 input projection: xw = x @ w_ih0^T + b_ih0 + b_hh0
    {
        dim3 grid(HH/128, RR/128);
        gemm_bias_kernel<<<grid, 256>>>(x, w_ih0, b_ih0, b_hh0, xw, RR, HH, CC);
    }
    // 2) layer-0 recurrence
    rnn_layer_kernel<<<NB_RNN, 1024, RNN_SMEM>>>(xw, h0, w_hh0, y0, TT);
    // 3) layer-1 input projection
    {
        dim3 grid(HH/128, RR/128);
        gemm_bias_kernel<<<grid, 256>>>(y0, w_ih1, b_ih1, b_hh1, xw, RR, HH, HH);
    }
    // 4) layer-1 recurrence
    rnn_layer_kernel<<<NB_RNN, 1024, RNN_SMEM>>>(xw, h0 + BB*HH, w_hh1, y1, TT);
    // 5) decoder
    {
        dim3 grid(CC/128, RR/128);
        gemm_bias_kernel<<<grid, 256>>>(y1, w_dec, b_dec, nullptr, out, RR, CC, HH);
    }
    // 6) hidden states appended after decoded
    gather_hidden_kernel<<<(2*BB*HH)/256, 256>>>(out + (size_t)TT*BB*CC);
}

// round 11
// speedup vs baseline: 1.2691x; 1.1002x over previous
#include <cuda_runtime.h>
#include <cuda_bf16.h>
#include <math.h>

#define TT 512
#define BB 64
#define CC 256
#define HH 1024
#define RR (TT*BB)

#define WPAD 36
#define HPAD 20
#define NB_RNN 128
#define RNN_SMEM (1024*WPAD*4 + 1024*HPAD*4 + 16*16*8)   // 231424 B

typedef unsigned long long ull;
typedef unsigned int uint;

// ---------------- packed fp32x2 helpers ----------------
#define PACKDUP(d, s) asm("mov.b64 %0, {%1, %1};" : "=l"(d) : "r"(__float_as_uint(s)))
#define FFMA2(acc, a, b) asm("fma.rn.f32x2 %0, %1, %2, %0;" : "+l"(acc) : "l"(a), "l"(b))
#define ADD2(d, a, b) asm("add.rn.f32x2 %0, %1, %2;" : "=l"(d) : "l"(a), "l"(b))
#define UNPACK2(lo, hi, v) asm("mov.b64 {%0, %1}, %2;" : "=r"(lo), "=r"(hi) : "l"(v))

// ---------------- scratch ----------------
__device__ float g_xw[(size_t)TT*BB*HH];
__device__ float g_y0[(size_t)TT*BB*HH];
__device__ float g_y1[(size_t)TT*BB*HH];
// bf16 split scratch: A (activations) and W (weights)
__device__ __nv_bfloat16 g_ah[(size_t)RR*HH];
__device__ __nv_bfloat16 g_al[(size_t)RR*HH];
__device__ __nv_bfloat16 g_wh[(size_t)HH*HH];
__device__ __nv_bfloat16 g_wl[(size_t)HH*HH];

// -------- per-batch-group grid barrier (monotonic, 4 domains of 32 CTAs) ---
__device__ unsigned g_cnt4[4*64];
__device__ unsigned g_gen4[4*64];

__device__ __forceinline__ unsigned ld_relaxed(const unsigned* p) {
    unsigned v;
    asm volatile("ld.relaxed.gpu.global.u32 %0, [%1];" : "=r"(v) : "l"(p) : "memory");
    return v;
}

__device__ __forceinline__ void group_sync(unsigned* cnt, unsigned* gen,
                                           unsigned target) {
    __syncthreads();
    if (threadIdx.x == 0) {
        unsigned old;
        asm volatile("atom.acq_rel.gpu.global.add.u32 %0, [%1], 1;"
                     : "=r"(old) : "l"(cnt) : "memory");
        if (old + 1u == 32u * target) {
            asm volatile("st.release.gpu.global.u32 [%0], %1;"
                         :: "l"(gen), "r"(target) : "memory");
        }
        unsigned v;
        do {
            asm volatile("ld.acquire.gpu.global.u32 %0, [%1];"
                         : "=r"(v) : "l"(gen) : "memory");
        } while ((int)(v - target) < 0);
    }
    __syncthreads();
}

// ---------------- bf16 split helpers ----------------
__device__ __forceinline__ uint packbf(float a, float b) {   // lo16=a, hi16=b
    uint r;
    asm("cvt.rn.bf16x2.f32 %0, %1, %2;" : "=r"(r) : "f"(b), "f"(a));
    return r;
}
__device__ __forceinline__ uint packlo(float a, float b, uint h) {
    float ha = __uint_as_float(h << 16);
    float hb = __uint_as_float(h & 0xFFFF0000u);
    return packbf(a - ha, b - hb);
}

// fp32 -> (bf16 hi, bf16 lo), 8 elements/thread
__global__ __launch_bounds__(256) void cvt_split_kernel(
    const float4* __restrict__ src, uint4* __restrict__ hi,
    uint4* __restrict__ lo, int n8)
{
    int i = blockIdx.x * 256 + threadIdx.x;
    if (i >= n8) return;
    float4 v0 = src[2*i], v1 = src[2*i + 1];
    uint h0 = packbf(v0.x, v0.y), h1 = packbf(v0.z, v0.w);
    uint h2 = packbf(v1.x, v1.y), h3 = packbf(v1.z, v1.w);
    uint l0 = packlo(v0.x, v0.y, h0), l1 = packlo(v0.z, v0.w, h1);
    uint l2 = packlo(v1.x, v1.y, h2), l3 = packlo(v1.z, v1.w, h3);
    hi[i] = make_uint4(h0, h1, h2, h3);
    lo[i] = make_uint4(l0, l1, l2, l3);
}

// ---------------- mma.sync bf16x3 GEMM ----------------
// out[R,N] = A[R,K] @ W[N,K]^T + b1(+b2); A,W given as bf16 hi/lo splits.
// CTA tile 128x128, 8 warps (2m x 4n, each 64x32), BK=32 double-buffered.
__device__ __forceinline__ uint smem_u32(const void* p) {
    uint a;
    asm("{ .reg .u64 t; cvta.to.shared.u64 t, %1; cvt.u32.u64 %0, t; }"
        : "=r"(a) : "l"(p));
    return a;
}

#define LDSM4(r, addr) \
    asm volatile("ldmatrix.sync.aligned.m8n8.x4.shared.b16 {%0,%1,%2,%3}, [%4];" \
        : "=r"((r)[0]), "=r"((r)[1]), "=r"((r)[2]), "=r"((r)[3]) : "r"(addr))

#define MMA16816(d, a, b0, b1v) \
    asm volatile("mma.sync.aligned.m16n8k16.row.col.f32.bf16.bf16.f32 " \
        "{%0,%1,%2,%3}, {%4,%5,%6,%7}, {%8,%9}, {%0,%1,%2,%3};" \
        : "+f"((d)[0]), "+f"((d)[1]), "+f"((d)[2]), "+f"((d)[3]) \
        : "r"((a)[0]), "r"((a)[1]), "r"((a)[2]), "r"((a)[3]), "r"(b0), "r"(b1v))

#define GSTR 40                    // smem row stride in bf16 (80 B)
#define TBLK (128*GSTR)            // one tensor block, bf16 elems (5120)
#define TBLKB (TBLK*2)             // bytes (10240)
#define GEMM_SMEM (2*4*TBLKB)      // 81920 B

#define STS128U(addr, a, b, c, d) \
    asm volatile("st.shared.v4.b32 [%0], {%1, %2, %3, %4};" \
                 :: "r"(addr), "r"(a), "r"(b), "r"(c), "r"(d) : "memory")

__global__ __launch_bounds__(256) void mma_gemm_kernel(
    const __nv_bfloat16* __restrict__ Ah, const __nv_bfloat16* __restrict__ Al,
    const __nv_bfloat16* __restrict__ Wh, const __nv_bfloat16* __restrict__ Wl,
    const float* __restrict__ b1, const float* __restrict__ b2,
    float* __restrict__ out, int N, int K)
{
    extern __shared__ char gsm[];
    const uint sbase = smem_u32(gsm);
    const int tid  = threadIdx.x;
    const int warp = tid >> 5;
    const int lane = tid & 31;
    const int c0 = blockIdx.x * 128;
    const int r0 = blockIdx.y * 128;
    const int wm = warp >> 2;          // 0..1 -> m rows wm*64
    const int wn = warp & 3;           // 0..3 -> n cols wn*32

    // loader mapping: thread t -> row (t&127) of A (t<128) or W (t>=128)
    const int lr = tid & 127;
    const __nv_bfloat16* gh0 = (tid < 128) ? (Ah + (size_t)(r0 + lr) * K)
                                           : (Wh + (size_t)(c0 + lr) * K);
    const __nv_bfloat16* gl0 = (tid < 128) ? (Al + (size_t)(r0 + lr) * K)
                                           : (Wl + (size_t)(c0 + lr) * K);
    const uint sdst_h = (tid < 128 ? 0u : 2u*TBLKB) + (uint)lr * (GSTR*2);

    // ldmatrix lane offsets (bytes)
    const uint aoff = (((lane & 7) + ((lane >> 3) & 1) * 8) * GSTR
                       + (lane >> 4) * 8) * 2;
    const uint boff = (((lane & 7) + (lane >> 4) * 8) * GSTR
                       + ((lane >> 3) & 1) * 8) * 2;

    float acc[4][4][4];
    #pragma unroll
    for (int m = 0; m < 4; m++)
        #pragma unroll
        for (int n = 0; n < 4; n++)
            #pragma unroll
            for (int q = 0; q < 4; q++) acc[m][n][q] = 0.f;

    const int nk = K / 32;

    // stage loader
    auto loadStage = [&](int kt, int s) {
        const __nv_bfloat16* gh = gh0 + kt * 32;
        const __nv_bfloat16* gl = gl0 + kt * 32;
        uint4 h0 = *(const uint4*)(gh);
        uint4 h1 = *(const uint4*)(gh + 8);
        uint4 h2 = *(const uint4*)(gh + 16);
        uint4 h3 = *(const uint4*)(gh + 24);
        uint4 q0 = *(const uint4*)(gl);
        uint4 q1 = *(const uint4*)(gl + 8);
        uint4 q2 = *(const uint4*)(gl + 16);
        uint4 q3 = *(const uint4*)(gl + 24);
        uint bh = sbase + (uint)s * (4*TBLKB) + sdst_h;
        uint bl = bh + TBLKB;
        STS128U(bh +  0, h0.x, h0.y, h0.z, h0.w);
        STS128U(bh + 16, h1.x, h1.y, h1.z, h1.w);
        STS128U(bh + 32, h2.x, h2.y, h2.z, h2.w);
        STS128U(bh + 48, h3.x, h3.y, h3.z, h3.w);
        STS128U(bl +  0, q0.x, q0.y, q0.z, q0.w);
        STS128U(bl + 16, q1.x, q1.y, q1.z, q1.w);
        STS128U(bl + 32, q2.x, q2.y, q2.z, q2.w);
        STS128U(bl + 48, q3.x, q3.y, q3.z, q3.w);
    };

    loadStage(0, 0);
    for (int kt = 0; kt < nk; kt++) {
        const int s = kt & 1;
        __syncthreads();
        if (kt + 1 < nk) loadStage(kt + 1, (kt + 1) & 1);

        const uint sb = sbase + (uint)s * (4*TBLKB);
        #pragma unroll
        for (int kb = 0; kb < 2; kb++) {
            const uint kbb = (uint)kb * 32;   // +16 bf16 = 32 B
            uint ah[4][4], al[4][4], bhf[2][4], blf[2][4];
            #pragma unroll
            for (int mt = 0; mt < 4; mt++) {
                uint ab = sb + ((uint)(wm*64 + mt*16) * GSTR) * 2 + kbb + aoff;
                LDSM4(ah[mt], ab);
                LDSM4(al[mt], ab + TBLKB);
            }
            #pragma unroll
            for (int nt2 = 0; nt2 < 2; nt2++) {
                uint bb = sb + 2u*TBLKB
                        + ((uint)(wn*32 + nt2*16) * GSTR) * 2 + kbb + boff;
                LDSM4(bhf[nt2], bb);
                LDSM4(blf[nt2], bb + TBLKB);
            }
            #pragma unroll
            for (int mt = 0; mt < 4; mt++)
                #pragma unroll
                for (int nt = 0; nt < 4; nt++) {
                    uint* bp = bhf[nt >> 1];
                    uint b0 = bp[(nt & 1) * 2], b1v = bp[(nt & 1) * 2 + 1];
                    MMA16816(acc[mt][nt], ah[mt], b0, b1v);
                }
            #pragma unroll
            for (int mt = 0; mt < 4; mt++)
                #pragma unroll
                for (int nt = 0; nt < 4; nt++) {
                    uint* bp = blf[nt >> 1];
                    uint b0 = bp[(nt & 1) * 2], b1v = bp[(nt & 1) * 2 + 1];
                    MMA16816(acc[mt][nt], ah[mt], b0, b1v);
                }
            #pragma unroll
            for (int mt = 0; mt < 4; mt++)
                #pragma unroll
                for (int nt = 0; nt < 4; nt++) {
                    uint* bp = bhf[nt >> 1];
                    uint b0 = bp[(nt & 1) * 2], b1v = bp[(nt & 1) * 2 + 1];
                    MMA16816(acc[mt][nt], al[mt], b0, b1v);
                }
        }
    }

    // epilogue
    const int rowb = r0 + wm*64 + (lane >> 2);
    const int colb = c0 + wn*32 + (lane & 3) * 2;
    #pragma unroll
    for (int nt = 0; nt < 4; nt++) {
        int col = colb + nt * 8;
        float bv0 = b1[col]     + (b2 ? b2[col]     : 0.f);
        float bv1 = b1[col + 1] + (b2 ? b2[col + 1] : 0.f);
        #pragma unroll
        for (int mt = 0; mt < 4; mt++) {
            int row = rowb + mt * 16;
            float2 o0 = make_float2(acc[mt][nt][0] + bv0, acc[mt][nt][1] + bv1);
            float2 o1 = make_float2(acc[mt][nt][2] + bv0, acc[mt][nt][3] + bv1);
            *(float2*)(out + (size_t)row * N + col)       = o0;
            *(float2*)(out + (size_t)(row + 8) * N + col) = o1;
        }
    }
}

// ------------- persistent recurrence (UNCHANGED from round 9) --------------
__global__ __launch_bounds__(1024) void rnn_layer_kernel(
    const float* __restrict__ xw, const float* __restrict__ h0,
    const float* __restrict__ Whh, float* __restrict__ y, int nsteps)
{
    extern __shared__ float smem[];
    float* Wsh = smem;
    float* hsm = smem + 1024*WPAD;
    ull*   sred = (ull*)(smem + 1024*WPAD + 1024*HPAD);

    const int tid = threadIdx.x;
    const int bid = blockIdx.x;
    const int cg  = bid & 31;
    const int bg  = bid >> 5;
    const int c0  = cg * 32;

    unsigned* cnt = &g_cnt4[bg*64];
    unsigned* gen = &g_gen4[bg*64];
    unsigned gen0 = ld_relaxed(gen);

    {
        const int j  = tid & 31;
        const int kc = tid >> 5;
        const float* wr = Whh + (size_t)(c0 + j) * HH + kc*32;
        #pragma unroll
        for (int i = 0; i < 8; i++) {
            float4 v = *(const float4*)(wr + i*4);
            int k = kc*32 + i*4;
            Wsh[(k+0)*WPAD + j] = v.x;
            Wsh[(k+1)*WPAD + j] = v.y;
            Wsh[(k+2)*WPAD + j] = v.z;
            Wsh[(k+3)*WPAD + j] = v.w;
        }
    }
    __syncthreads();

    const int sb   = tid & 15;
    const int skc  = tid >> 4;
    const int warp = tid >> 5;
    const int lane = tid & 31;
    const int half = warp >> 4;
    const int wt   = warp & 15;
    const int bl0  = (wt >> 2) * 4;
    const int jl0  = (wt & 3) * 8;
    const int kbase = half * 512;
    const int p    = (lane >> 1) & 15;
    const int eb   = bl0 + (p >> 2);
    const int ej   = jl0 + (p & 3) * 2;

    for (int t = 0; t < nsteps; t++) {
        const float* hprev = (t == 0) ? h0 : (y + (size_t)(t-1)*BB*HH);

        size_t oidx = ((size_t)t*BB + bg*16 + eb)*HH + c0 + ej;
        float2 xwv = *(const float2*)&xw[oidx];

        {
            const float* hr = hprev + (size_t)(bg*16 + sb)*HH + skc*16;
            #pragma unroll
            for (int i = 0; i < 4; i++) {
                float4 v = *(const float4*)(hr + i*4);
                int k = skc*16 + i*4;
                hsm[(k+0)*HPAD + sb] = v.x;
                hsm[(k+1)*HPAD + sb] = v.y;
                hsm[(k+2)*HPAD + sb] = v.z;
                hsm[(k+3)*HPAD + sb] = v.w;
            }
        }
        __syncthreads();

        ull v[16];
        #pragma unroll
        for (int i = 0; i < 16; i++) v[i] = 0ull;

        #pragma unroll 4
        for (int i = 0; i < 16; i++) {
            int k = kbase + i*32 + lane;
            float4 hv = *(const float4*)&hsm[k*HPAD + bl0];
            ulonglong2 wv0 = *(const ulonglong2*)&Wsh[k*WPAD + jl0];
            ulonglong2 wv1 = *(const ulonglong2*)&Wsh[k*WPAD + jl0 + 4];
            ull wp0 = wv0.x, wp1 = wv0.y, wp2 = wv1.x, wp3 = wv1.y;
            float hr4[4] = {hv.x, hv.y, hv.z, hv.w};
            #pragma unroll
            for (int r = 0; r < 4; r++) {
                ull hd; PACKDUP(hd, hr4[r]);
                FFMA2(v[r*4+0], hd, wp0);
                FFMA2(v[r*4+1], hd, wp1);
                FFMA2(v[r*4+2], hd, wp2);
                FFMA2(v[r*4+3], hd, wp3);
            }
        }

        #pragma unroll
        for (int si = 0; si < 4; si++) {
            const int s  = 16 >> si;
            const int nv = 8 >> si;
            const bool up = lane & s;
            #pragma unroll
            for (int i = 0; i < nv; i++) {
                ull give = up ? v[i] : v[i + nv];
                ull got  = __shfl_xor_sync(0xFFFFFFFFu, give, s);
                ull keep = up ? v[i + nv] : v[i];
                ADD2(v[i], keep, got);
            }
        }
        {
            ull got = __shfl_xor_sync(0xFFFFFFFFu, v[0], 1);
            ADD2(v[0], v[0], got);
        }

        if (half && !(lane & 1)) sred[wt*16 + p] = v[0];
        __syncthreads();
        if (!half && !(lane & 1)) {
            ADD2(v[0], v[0], sred[wt*16 + p]);
            unsigned lo, hi;
            UNPACK2(lo, hi, v[0]);
            float2 rv;
            rv.x = tanhf(xwv.x + __uint_as_float(lo));
            rv.y = tanhf(xwv.y + __uint_as_float(hi));
            *(float2*)&y[oidx] = rv;
        }

        group_sync(cnt, gen, gen0 + (unsigned)t + 1u);
    }
}

// ------------- hidden-state gather ----------------
__global__ void gather_hidden_kernel(float* __restrict__ out_hidden)
{
    int i = blockIdx.x * blockDim.x + threadIdx.x;
    const float* src = (i < BB*HH)
        ? (g_y0 + (size_t)(TT-1)*BB*HH + i)
        : (g_y1 + (size_t)(TT-1)*BB*HH + (i - BB*HH));
    out_hidden[i] = *src;
}

extern "C" void kernel_launch(void* const* d_in, const int* in_sizes, int n_in,
                              void* d_out, int out_size) {
    const float* x     = (const float*)d_in[0];
    const float* h0    = (const float*)d_in[1];
    const float* w_ih0 = (const float*)d_in[2];
    const float* w_hh0 = (const float*)d_in[3];
    const float* b_ih0 = (const float*)d_in[4];
    const float* b_hh0 = (const float*)d_in[5];
    const float* w_ih1 = (const float*)d_in[6];
    const float* w_hh1 = (const float*)d_in[7];
    const float* b_ih1 = (const float*)d_in[8];
    const float* b_hh1 = (const float*)d_in[9];
    const float* w_dec = (const float*)d_in[10];
    const float* b_dec = (const float*)d_in[11];
    float* out = (float*)d_out;

    cudaFuncSetAttribute(rnn_layer_kernel,
                         cudaFuncAttributeMaxDynamicSharedMemorySize, RNN_SMEM);
    cudaFuncSetAttribute(mma_gemm_kernel,
                         cudaFuncAttributeMaxDynamicSharedMemorySize, GEMM_SMEM);

    float* xw;  cudaGetSymbolAddress((void**)&xw,  g_xw);
    float* y0;  cudaGetSymbolAddress((void**)&y0,  g_y0);
    float* y1;  cudaGetSymbolAddress((void**)&y1,  g_y1);
    __nv_bfloat16 *ah, *al, *wh, *wl;
    cudaGetSymbolAddress((void**)&ah, g_ah);
    cudaGetSymbolAddress((void**)&al, g_al);
    cudaGetSymbolAddress((void**)&wh, g_wh);
    cudaGetSymbolAddress((void**)&wl, g_wl);

    // 1) split x and w_ih0; layer-0 input projection
    cvt_split_kernel<<<RR*CC/8/256, 256>>>((const float4*)x, (uint4*)ah, (uint4*)al, RR*CC/8);
    cvt_split_kernel<<<HH*CC/8/256, 256>>>((const float4*)w_ih0, (uint4*)wh, (uint4*)wl, HH*CC/8);
    {
        dim3 grid(HH/128, RR/128);
        mma_gemm_kernel<<<grid, 256, GEMM_SMEM>>>(ah, al, wh, wl, b_ih0, b_hh0, xw, HH, CC);
    }
    // 2) layer-0 recurrence
    rnn_layer_kernel<<<NB_RNN, 1024, RNN_SMEM>>>(xw, h0, w_hh0, y0, TT);
    // 3) split y0 and w_ih1; layer-1 input projection
    cvt_split_kernel<<<RR*HH/8/256, 256>>>((const float4*)y0, (uint4*)ah, (uint4*)al, RR*HH/8);
    cvt_split_kernel<<<HH*HH/8/256, 256>>>((const float4*)w_ih1, (uint4*)wh, (uint4*)wl, HH*HH/8);
    {
        dim3 grid(HH/128, RR/128);
        mma_gemm_kernel<<<grid, 256, GEMM_SMEM>>>(ah, al, wh, wl, b_ih1, b_hh1, xw, HH, HH);
    }
    // 4) layer-1 recurrence
    rnn_layer_kernel<<<NB_RNN, 1024, RNN_SMEM>>>(xw, h0 + BB*HH, w_hh1, y1, TT);
    // 5) split y1 and w_dec; decoder
    cvt_split_kernel<<<RR*HH/8/256, 256>>>((const float4*)y1, (uint4*)ah, (uint4*)al, RR*HH/8);
    cvt_split_kernel<<<CC*HH/8/256, 256>>>((const float4*)w_dec, (uint4*)wh, (uint4*)wl, CC*HH/8);
    {
        dim3 grid(CC/128, RR/128);
        mma_gemm_kernel<<<grid, 256, GEMM_SMEM>>>(ah, al, wh, wl, b_dec, nullptr, out, CC, HH);
    }
    // 6) hidden states appended after decoded
    gather_hidden_kernel<<<(2*BB*HH)/256, 256>>>(out + (size_t)TT*BB*CC);
}

// round 12
// speedup vs baseline: 1.7417x; 1.3724x over previous
#include <cuda_runtime.h>
#include <cuda_bf16.h>
#include <math.h>

#define TT 512
#define BB 64
#define CC 256
#define HH 1024
#define RR (TT*BB)
#define BBHH (BB*HH)

#define NB_RNN 128
#define HSTR 1032                         // bf16 row stride (2064 B)
#define HS_BYTES (16*HSTR*2)              // one h buffer (hi or lo): 33024
#define RED_OFF (2*HS_BYTES)              // 66048
#define RNN2_SMEM (RED_OFF + 28*32*16)    // + red 14336 = 80384

typedef unsigned long long ull;
typedef unsigned int uint;

// ---------------- scratch ----------------
__device__ float g_xw[(size_t)TT*BB*HH];
__device__ float g_y0[(size_t)TT*BB*HH];
__device__ float g_y1[(size_t)TT*BB*HH];
// bf16 hi/lo activation arrays; slot 0 = initial h, slot t+1 = y[t]
__device__ __nv_bfloat16 g_y0h[(size_t)(TT+1)*BBHH];
__device__ __nv_bfloat16 g_y0l[(size_t)(TT+1)*BBHH];
__device__ __nv_bfloat16 g_y1h[(size_t)(TT+1)*BBHH];
__device__ __nv_bfloat16 g_y1l[(size_t)(TT+1)*BBHH];
// bf16 split scratch for GEMM inputs (x) and weights
__device__ __nv_bfloat16 g_ah[(size_t)RR*CC];
__device__ __nv_bfloat16 g_al[(size_t)RR*CC];
__device__ __nv_bfloat16 g_wh[(size_t)HH*HH];
__device__ __nv_bfloat16 g_wl[(size_t)HH*HH];

// -------- per-batch-group grid barrier (monotonic, 4 domains of 32 CTAs) ---
__device__ unsigned g_cnt4[4*64];
__device__ unsigned g_gen4[4*64];

__device__ __forceinline__ unsigned ld_relaxed(const unsigned* p) {
    unsigned v;
    asm volatile("ld.relaxed.gpu.global.u32 %0, [%1];" : "=r"(v) : "l"(p) : "memory");
    return v;
}

__device__ __forceinline__ void group_sync(unsigned* cnt, unsigned* gen,
                                           unsigned target) {
    __syncthreads();
    if (threadIdx.x == 0) {
        unsigned old;
        asm volatile("atom.acq_rel.gpu.global.add.u32 %0, [%1], 1;"
                     : "=r"(old) : "l"(cnt) : "memory");
        if (old + 1u == 32u * target) {
            asm volatile("st.release.gpu.global.u32 [%0], %1;"
                         :: "l"(gen), "r"(target) : "memory");
        }
        unsigned v;
        do {
            asm volatile("ld.acquire.gpu.global.u32 %0, [%1];"
                         : "=r"(v) : "l"(gen) : "memory");
        } while ((int)(v - target) < 0);
    }
    __syncthreads();
}

// ---------------- bf16 split helpers ----------------
__device__ __forceinline__ uint packbf(float a, float b) {   // lo16=a, hi16=b
    uint r;
    asm("cvt.rn.bf16x2.f32 %0, %1, %2;" : "=r"(r) : "f"(b), "f"(a));
    return r;
}
__device__ __forceinline__ uint packlo(float a, float b, uint h) {
    float ha = __uint_as_float(h << 16);
    float hb = __uint_as_float(h & 0xFFFF0000u);
    return packbf(a - ha, b - hb);
}

// fp32 -> (bf16 hi, bf16 lo), 8 elements/thread
__global__ __launch_bounds__(256) void cvt_split_kernel(
    const float4* __restrict__ src, uint4* __restrict__ hi,
    uint4* __restrict__ lo, int n8)
{
    int i = blockIdx.x * 256 + threadIdx.x;
    if (i >= n8) return;
    float4 v0 = src[2*i], v1 = src[2*i + 1];
    uint h0 = packbf(v0.x, v0.y), h1 = packbf(v0.z, v0.w);
    uint h2 = packbf(v1.x, v1.y), h3 = packbf(v1.z, v1.w);
    uint l0 = packlo(v0.x, v0.y, h0), l1 = packlo(v0.z, v0.w, h1);
    uint l2 = packlo(v1.x, v1.y, h2), l3 = packlo(v1.z, v1.w, h3);
    hi[i] = make_uint4(h0, h1, h2, h3);
    lo[i] = make_uint4(l0, l1, l2, l3);
}

// ---------------- shared mma plumbing ----------------
__device__ __forceinline__ uint smem_u32(const void* p) {
    uint a;
    asm("{ .reg .u64 t; cvta.to.shared.u64 t, %1; cvt.u32.u64 %0, t; }"
        : "=r"(a) : "l"(p));
    return a;
}

#define LDSM4(r, addr) \
    asm volatile("ldmatrix.sync.aligned.m8n8.x4.shared.b16 {%0,%1,%2,%3}, [%4];" \
        : "=r"((r)[0]), "=r"((r)[1]), "=r"((r)[2]), "=r"((r)[3]) : "r"(addr))

#define MMA16816(d, a, b0, b1v) \
    asm volatile("mma.sync.aligned.m16n8k16.row.col.f32.bf16.bf16.f32 " \
        "{%0,%1,%2,%3}, {%4,%5,%6,%7}, {%8,%9}, {%0,%1,%2,%3};" \
        : "+f"((d)[0]), "+f"((d)[1]), "+f"((d)[2]), "+f"((d)[3]) \
        : "r"((a)[0]), "r"((a)[1]), "r"((a)[2]), "r"((a)[3]), "r"(b0), "r"(b1v))

#define STS128U(addr, a, b, c, d) \
    asm volatile("st.shared.v4.b32 [%0], {%1, %2, %3, %4};" \
                 :: "r"(addr), "r"(a), "r"(b), "r"(c), "r"(d) : "memory")

// ---------------- mma.sync bf16x3 GEMM (UNCHANGED from r11) ----------------
#define GSTR 40
#define TBLK (128*GSTR)
#define TBLKB (TBLK*2)
#define GEMM_SMEM (2*4*TBLKB)

__global__ __launch_bounds__(256) void mma_gemm_kernel(
    const __nv_bfloat16* __restrict__ Ah, const __nv_bfloat16* __restrict__ Al,
    const __nv_bfloat16* __restrict__ Wh, const __nv_bfloat16* __restrict__ Wl,
    const float* __restrict__ b1, const float* __restrict__ b2,
    float* __restrict__ out, int N, int K)
{
    extern __shared__ char gsm[];
    const uint sbase = smem_u32(gsm);
    const int tid  = threadIdx.x;
    const int warp = tid >> 5;
    const int lane = tid & 31;
    const int c0 = blockIdx.x * 128;
    const int r0 = blockIdx.y * 128;
    const int wm = warp >> 2;
    const int wn = warp & 3;

    const int lr = tid & 127;
    const __nv_bfloat16* gh0 = (tid < 128) ? (Ah + (size_t)(r0 + lr) * K)
                                           : (Wh + (size_t)(c0 + lr) * K);
    const __nv_bfloat16* gl0 = (tid < 128) ? (Al + (size_t)(r0 + lr) * K)
                                           : (Wl + (size_t)(c0 + lr) * K);
    const uint sdst_h = (tid < 128 ? 0u : 2u*TBLKB) + (uint)lr * (GSTR*2);

    const uint aoff = (((lane & 7) + ((lane >> 3) & 1) * 8) * GSTR
                       + (lane >> 4) * 8) * 2;
    const uint boff = (((lane & 7) + (lane >> 4) * 8) * GSTR
                       + ((lane >> 3) & 1) * 8) * 2;

    float acc[4][4][4];
    #pragma unroll
    for (int m = 0; m < 4; m++)
        #pragma unroll
        for (int n = 0; n < 4; n++)
            #pragma unroll
            for (int q = 0; q < 4; q++) acc[m][n][q] = 0.f;

    const int nk = K / 32;

    auto loadStage = [&](int kt, int s) {
        const __nv_bfloat16* gh = gh0 + kt * 32;
        const __nv_bfloat16* gl = gl0 + kt * 32;
        uint4 h0 = *(const uint4*)(gh);
        uint4 h1 = *(const uint4*)(gh + 8);
        uint4 h2 = *(const uint4*)(gh + 16);
        uint4 h3 = *(const uint4*)(gh + 24);
        uint4 q0 = *(const uint4*)(gl);
        uint4 q1 = *(const uint4*)(gl + 8);
        uint4 q2 = *(const uint4*)(gl + 16);
        uint4 q3 = *(const uint4*)(gl + 24);
        uint bh = sbase + (uint)s * (4*TBLKB) + sdst_h;
        uint bl = bh + TBLKB;
        STS128U(bh +  0, h0.x, h0.y, h0.z, h0.w);
        STS128U(bh + 16, h1.x, h1.y, h1.z, h1.w);
        STS128U(bh + 32, h2.x, h2.y, h2.z, h2.w);
        STS128U(bh + 48, h3.x, h3.y, h3.z, h3.w);
        STS128U(bl +  0, q0.x, q0.y, q0.z, q0.w);
        STS128U(bl + 16, q1.x, q1.y, q1.z, q1.w);
        STS128U(bl + 32, q2.x, q2.y, q2.z, q2.w);
        STS128U(bl + 48, q3.x, q3.y, q3.z, q3.w);
    };

    loadStage(0, 0);
    for (int kt = 0; kt < nk; kt++) {
        const int s = kt & 1;
        __syncthreads();
        if (kt + 1 < nk) loadStage(kt + 1, (kt + 1) & 1);

        const uint sb = sbase + (uint)s * (4*TBLKB);
        #pragma unroll
        for (int kb = 0; kb < 2; kb++) {
            const uint kbb = (uint)kb * 32;
            uint ah[4][4], al[4][4], bhf[2][4], blf[2][4];
            #pragma unroll
            for (int mt = 0; mt < 4; mt++) {
                uint ab = sb + ((uint)(wm*64 + mt*16) * GSTR) * 2 + kbb + aoff;
                LDSM4(ah[mt], ab);
                LDSM4(al[mt], ab + TBLKB);
            }
            #pragma unroll
            for (int nt2 = 0; nt2 < 2; nt2++) {
                uint bb = sb + 2u*TBLKB
                        + ((uint)(wn*32 + nt2*16) * GSTR) * 2 + kbb + boff;
                LDSM4(bhf[nt2], bb);
                LDSM4(blf[nt2], bb + TBLKB);
            }
            #pragma unroll
            for (int mt = 0; mt < 4; mt++)
                #pragma unroll
                for (int nt = 0; nt < 4; nt++) {
                    uint* bp = bhf[nt >> 1];
                    MMA16816(acc[mt][nt], ah[mt], bp[(nt & 1) * 2], bp[(nt & 1) * 2 + 1]);
                }
            #pragma unroll
            for (int mt = 0; mt < 4; mt++)
                #pragma unroll
                for (int nt = 0; nt < 4; nt++) {
                    uint* bp = blf[nt >> 1];
                    MMA16816(acc[mt][nt], ah[mt], bp[(nt & 1) * 2], bp[(nt & 1) * 2 + 1]);
                }
            #pragma unroll
            for (int mt = 0; mt < 4; mt++)
                #pragma unroll
                for (int nt = 0; nt < 4; nt++) {
                    uint* bp = bhf[nt >> 1];
                    MMA16816(acc[mt][nt], al[mt], bp[(nt & 1) * 2], bp[(nt & 1) * 2 + 1]);
                }
        }
    }

    const int rowb = r0 + wm*64 + (lane >> 2);
    const int colb = c0 + wn*32 + (lane & 3) * 2;
    #pragma unroll
    for (int nt = 0; nt < 4; nt++) {
        int col = colb + nt * 8;
        float bv0 = b1[col]     + (b2 ? b2[col]     : 0.f);
        float bv1 = b1[col + 1] + (b2 ? b2[col + 1] : 0.f);
        #pragma unroll
        for (int mt = 0; mt < 4; mt++) {
            int row = rowb + mt * 16;
            float2 o0 = make_float2(acc[mt][nt][0] + bv0, acc[mt][nt][1] + bv1);
            float2 o1 = make_float2(acc[mt][nt][2] + bv0, acc[mt][nt][3] + bv1);
            *(float2*)(out + (size_t)row * N + col)       = o0;
            *(float2*)(out + (size_t)(row + 8) * N + col) = o1;
        }
    }
}

// ------------- persistent recurrence, tensor-core + register-W -------------
// 128 CTAs = 4 bg(16 batch) x 32 cg(32 cols). 1024 thr = 32 warps.
// warp = (kg 0..7)*4 + (nt 0..3). W_hh slice lives in REGISTERS as bf16 hi/lo
// B-fragments. h staged in smem as bf16 hi/lo (written by prev step epilogue).
// bf16x3: Ah*Wh + Ah*Wl + Al*Wh, fp32 accum. 8-way k-split reduced via smem.
__global__ __launch_bounds__(1024) void rnn_mma_kernel(
    const float* __restrict__ xw,
    __nv_bfloat16* __restrict__ yh, __nv_bfloat16* __restrict__ yl,
    float* __restrict__ yfp, const float* __restrict__ Whh, int nsteps)
{
    extern __shared__ char smemc[];
    const uint hbase = smem_u32(smemc);
    float* redf = (float*)(smemc + RED_OFF);   // [28 warps][32 lanes][4]

    const int tid = threadIdx.x;
    const int bid = blockIdx.x;
    const int cg  = bid & 31;
    const int bg  = bid >> 5;
    const int c0  = cg * 32;
    const int warp = tid >> 5;
    const int lane = tid & 31;
    const int kg  = warp >> 2;       // k-split 0..7 (128 k each)
    const int nt  = warp & 3;        // n-tile 0..3 (8 cols each)

    unsigned* cnt = &g_cnt4[bg*64];
    unsigned* gen = &g_gen4[bg*64];
    unsigned gen0 = ld_relaxed(gen);

    // ---- one-time: W B-fragments into registers (bf16 hi/lo) ----
    const int nW = c0 + nt*8 + (lane >> 2);
    const int kW = kg*128 + 2*(lane & 3);
    uint whi0[8], whi1[8], wlo0[8], wlo1[8];
    #pragma unroll
    for (int kt = 0; kt < 8; kt++) {
        const float* wp = Whh + (size_t)nW * HH + kW + kt*16;
        float2 w0 = *(const float2*)(wp);
        float2 w1 = *(const float2*)(wp + 8);
        whi0[kt] = packbf(w0.x, w0.y); wlo0[kt] = packlo(w0.x, w0.y, whi0[kt]);
        whi1[kt] = packbf(w1.x, w1.y); wlo1[kt] = packlo(w1.x, w1.y, whi1[kt]);
    }

    // staging: thread -> 16 k of one batch row (hi + lo)
    const int sb  = tid & 15;
    const int skc = tid >> 4;        // 0..63
    const uint sdst = hbase + (uint)sb * (HSTR*2) + (uint)skc * 32;

    // ldmatrix A offset
    const uint aoff = (uint)(((lane & 7) + ((lane >> 3) & 1) * 8) * (HSTR*2)
                             + (lane >> 4) * 16);

    // epilogue mapping (D-frag): rows bg*16 + (lane>>2) (+8), cols c0+nt*8+(lane&3)*2
    const int erow = bg*16 + (lane >> 2);
    const int ecol = c0 + nt*8 + (lane & 3)*2;

    for (int t = 0; t < nsteps; t++) {
        // prefetch xw for epilogue (reducing warps only)
        size_t idx0 = ((size_t)t*BB + erow)*HH + ecol;
        float2 xw0, xw8;
        if (kg == 0) {
            xw0 = *(const float2*)&xw[idx0];
            xw8 = *(const float2*)&xw[idx0 + 8*HH];
        }

        // stage h (hi/lo bf16) from slot t
        {
            const __nv_bfloat16* sh = yh + (size_t)t*BBHH
                                      + (size_t)(bg*16 + sb)*HH + skc*16;
            const __nv_bfloat16* sl = yl + (size_t)t*BBHH
                                      + (size_t)(bg*16 + sb)*HH + skc*16;
            uint4 a0 = *(const uint4*)sh;
            uint4 a1 = *(const uint4*)(sh + 8);
            uint4 b0 = *(const uint4*)sl;
            uint4 b1 = *(const uint4*)(sl + 8);
            STS128U(sdst,      a0.x, a0.y, a0.z, a0.w);
            STS128U(sdst + 16, a1.x, a1.y, a1.z, a1.w);
            STS128U(sdst + HS_BYTES,      b0.x, b0.y, b0.z, b0.w);
            STS128U(sdst + HS_BYTES + 16, b1.x, b1.y, b1.z, b1.w);
        }
        __syncthreads();

        float acc[4] = {0.f, 0.f, 0.f, 0.f};
        #pragma unroll
        for (int kt = 0; kt < 8; kt++) {
            uint ab = hbase + (uint)((kg*128 + kt*16) * 2) + aoff;
            uint Ah[4], Al[4];
            LDSM4(Ah, ab);
            MMA16816(acc, Ah, whi0[kt], whi1[kt]);   // Ah*Wh
            MMA16816(acc, Ah, wlo0[kt], wlo1[kt]);   // Ah*Wl
            LDSM4(Al, ab + HS_BYTES);
            MMA16816(acc, Al, whi0[kt], whi1[kt]);   // Al*Wh
        }

        // k-split reduction via smem (warps kg>0 store; kg==0 reduces)
        if (kg) *(float4*)(redf + (warp - 4)*128 + lane*4) = *(float4*)acc;
        __syncthreads();
        if (kg == 0) {
            #pragma unroll
            for (int k = 1; k < 8; k++) {
                float4 o = *(float4*)(redf + (k*4 + nt - 4)*128 + lane*4);
                acc[0] += o.x; acc[1] += o.y; acc[2] += o.z; acc[3] += o.w;
            }
            float t0 = tanhf(xw0.x + acc[0]);
            float t1 = tanhf(xw0.y + acc[1]);
            float t2 = tanhf(xw8.x + acc[2]);
            float t3 = tanhf(xw8.y + acc[3]);
            uint h01 = packbf(t0, t1), l01 = packlo(t0, t1, h01);
            uint h23 = packbf(t2, t3), l23 = packlo(t2, t3, h23);
            size_t o0 = idx0 + BBHH;          // slot t+1
            *(uint*)&yh[o0]          = h01;
            *(uint*)&yl[o0]          = l01;
            *(uint*)&yh[o0 + 8*HH]   = h23;
            *(uint*)&yl[o0 + 8*HH]   = l23;
            if (t == nsteps - 1) {
                *(float2*)&yfp[idx0]          = make_float2(t0, t1);
                *(float2*)&yfp[idx0 + 8*HH]   = make_float2(t2, t3);
            }
        }

        group_sync(cnt, gen, gen0 + (unsigned)t + 1u);
    }
}

// ------------- hidden-state gather ----------------
__global__ void gather_hidden_kernel(float* __restrict__ out_hidden)
{
    int i = blockIdx.x * blockDim.x + threadIdx.x;
    const float* src = (i < BBHH)
        ? (g_y0 + (size_t)(TT-1)*BBHH + i)
        : (g_y1 + (size_t)(TT-1)*BBHH + (i - BBHH));
    out_hidden[i] = *src;
}

extern "C" void kernel_launch(void* const* d_in, const int* in_sizes, int n_in,
                              void* d_out, int out_size) {
    const float* x     = (const float*)d_in[0];
    const float* h0    = (const float*)d_in[1];
    const float* w_ih0 = (const float*)d_in[2];
    const float* w_hh0 = (const float*)d_in[3];
    const float* b_ih0 = (const float*)d_in[4];
    const float* b_hh0 = (const float*)d_in[5];
    const float* w_ih1 = (const float*)d_in[6];
    const float* w_hh1 = (const float*)d_in[7];
    const float* b_ih1 = (const float*)d_in[8];
    const float* b_hh1 = (const float*)d_in[9];
    const float* w_dec = (const float*)d_in[10];
    const float* b_dec = (const float*)d_in[11];
    float* out = (float*)d_out;

    cudaFuncSetAttribute(rnn_mma_kernel,
                         cudaFuncAttributeMaxDynamicSharedMemorySize, RNN2_SMEM);
    cudaFuncSetAttribute(mma_gemm_kernel,
                         cudaFuncAttributeMaxDynamicSharedMemorySize, GEMM_SMEM);

    float* xw;  cudaGetSymbolAddress((void**)&xw,  g_xw);
    float* y0;  cudaGetSymbolAddress((void**)&y0,  g_y0);
    float* y1;  cudaGetSymbolAddress((void**)&y1,  g_y1);
    __nv_bfloat16 *ah, *al, *wh, *wl, *y0h, *y0l, *y1h, *y1l;
    cudaGetSymbolAddress((void**)&ah,  g_ah);
    cudaGetSymbolAddress((void**)&al,  g_al);
    cudaGetSymbolAddress((void**)&wh,  g_wh);
    cudaGetSymbolAddress((void**)&wl,  g_wl);
    cudaGetSymbolAddress((void**)&y0h, g_y0h);
    cudaGetSymbolAddress((void**)&y0l, g_y0l);
    cudaGetSymbolAddress((void**)&y1h, g_y1h);
    cudaGetSymbolAddress((void**)&y1l, g_y1l);

    // 0) split x, w_ih0, and both h0 slices (h0 -> slot 0 of yh/yl arrays)
    cvt_split_kernel<<<RR*CC/8/256, 256>>>((const float4*)x, (uint4*)ah, (uint4*)al, RR*CC/8);
    cvt_split_kernel<<<HH*CC/8/256, 256>>>((const float4*)w_ih0, (uint4*)wh, (uint4*)wl, HH*CC/8);
    cvt_split_kernel<<<BBHH/8/256, 256>>>((const float4*)h0, (uint4*)y0h, (uint4*)y0l, BBHH/8);
    cvt_split_kernel<<<BBHH/8/256, 256>>>((const float4*)(h0 + BBHH), (uint4*)y1h, (uint4*)y1l, BBHH/8);

    // 1) layer-0 input projection: xw = x @ w_ih0^T + b_ih0 + b_hh0
    {
        dim3 grid(HH/128, RR/128);
        mma_gemm_kernel<<<grid, 256, GEMM_SMEM>>>(ah, al, wh, wl, b_ih0, b_hh0, xw, HH, CC);
    }
    // 2) layer-0 recurrence (writes y0h/y0l slots 1.., fp32 y0 at last step)
    rnn_mma_kernel<<<NB_RNN, 1024, RNN2_SMEM>>>(xw, y0h, y0l, y0, w_hh0, TT);
    // 3) layer-1 input projection (A = y0 hi/lo slots 1..512 directly)
    cvt_split_kernel<<<HH*HH/8/256, 256>>>((const float4*)w_ih1, (uint4*)wh, (uint4*)wl, HH*HH/8);
    {
        dim3 grid(HH/128, RR/128);
        mma_gemm_kernel<<<grid, 256, GEMM_SMEM>>>(y0h + BBHH, y0l + BBHH, wh, wl,
                                                  b_ih1, b_hh1, xw, HH, HH);
    }
    // 4) layer-1 recurrence
    rnn_mma_kernel<<<NB_RNN, 1024, RNN2_SMEM>>>(xw, y1h, y1l, y1, w_hh1, TT);
    // 5) decoder (A = y1 hi/lo slots 1..512)
    cvt_split_kernel<<<CC*HH/8/256, 256>>>((const float4*)w_dec, (uint4*)wh, (uint4*)wl, CC*HH/8);
    {
        dim3 grid(CC/128, RR/128);
        mma_gemm_kernel<<<grid, 256, GEMM_SMEM>>>(y1h + BBHH, y1l + BBHH, wh, wl,
                                                  b_dec, nullptr, out, CC, HH);
    }
    // 6) hidden states appended after decoded
    gather_hidden_kernel<<<(2*BBHH)/256, 256>>>(out + (size_t)TT*BB*CC);
}

// round 13
// speedup vs baseline: 1.9534x; 1.1216x over previous
#include <cuda_runtime.h>
#include <cuda_bf16.h>
#include <math.h>

#define TT 512
#define BB 64
#define CC 256
#define HH 1024
#define RR (TT*BB)
#define BBHH (BB*HH)

#define NB_RNN 128
#define HSTR 1032                         // bf16 row stride (2064 B)
#define HS_BYTES (16*HSTR*2)              // one h buffer (hi or lo): 33024
#define RED_OFF (2*HS_BYTES)              // 66048
#define RNN2_SMEM (RED_OFF + 28*32*16)    // + red 14336 = 80384

typedef unsigned long long ull;
typedef unsigned int uint;

// ---------------- scratch ----------------
__device__ float g_xw[(size_t)TT*BB*HH];
__device__ float g_y0[(size_t)TT*BB*HH];
__device__ float g_y1[(size_t)TT*BB*HH];
// bf16 hi/lo activation arrays; slot 0 = initial h, slot t+1 = y[t]
__device__ __nv_bfloat16 g_y0h[(size_t)(TT+1)*BBHH];
__device__ __nv_bfloat16 g_y0l[(size_t)(TT+1)*BBHH];
__device__ __nv_bfloat16 g_y1h[(size_t)(TT+1)*BBHH];
__device__ __nv_bfloat16 g_y1l[(size_t)(TT+1)*BBHH];
// bf16 split scratch for GEMM inputs (x) and weights
__device__ __nv_bfloat16 g_ah[(size_t)RR*CC];
__device__ __nv_bfloat16 g_al[(size_t)RR*CC];
__device__ __nv_bfloat16 g_wh[(size_t)HH*HH];
__device__ __nv_bfloat16 g_wl[(size_t)HH*HH];

// -------- per-batch-group grid barrier (monotonic, 4 domains of 32 CTAs) ---
__device__ unsigned g_cnt4[4*64];
__device__ unsigned g_gen4[4*64];

__device__ __forceinline__ unsigned ld_relaxed(const unsigned* p) {
    unsigned v;
    asm volatile("ld.relaxed.gpu.global.u32 %0, [%1];" : "=r"(v) : "l"(p) : "memory");
    return v;
}

__device__ __forceinline__ void group_sync(unsigned* cnt, unsigned* gen,
                                           unsigned target) {
    __syncthreads();
    if (threadIdx.x == 0) {
        unsigned old;
        asm volatile("atom.acq_rel.gpu.global.add.u32 %0, [%1], 1;"
                     : "=r"(old) : "l"(cnt) : "memory");
        if (old + 1u == 32u * target) {
            asm volatile("st.release.gpu.global.u32 [%0], %1;"
                         :: "l"(gen), "r"(target) : "memory");
        }
        unsigned v;
        do {
            asm volatile("ld.acquire.gpu.global.u32 %0, [%1];"
                         : "=r"(v) : "l"(gen) : "memory");
        } while ((int)(v - target) < 0);
    }
    __syncthreads();
}

// ---------------- bf16 split helpers ----------------
__device__ __forceinline__ uint packbf(float a, float b) {   // lo16=a, hi16=b
    uint r;
    asm("cvt.rn.bf16x2.f32 %0, %1, %2;" : "=r"(r) : "f"(b), "f"(a));
    return r;
}
__device__ __forceinline__ uint packlo(float a, float b, uint h) {
    float ha = __uint_as_float(h << 16);
    float hb = __uint_as_float(h & 0xFFFF0000u);
    return packbf(a - ha, b - hb);
}

// fp32 -> (bf16 hi, bf16 lo), 8 elements/thread
__global__ __launch_bounds__(256) void cvt_split_kernel(
    const float4* __restrict__ src, uint4* __restrict__ hi,
    uint4* __restrict__ lo, int n8)
{
    int i = blockIdx.x * 256 + threadIdx.x;
    if (i >= n8) return;
    float4 v0 = src[2*i], v1 = src[2*i + 1];
    uint h0 = packbf(v0.x, v0.y), h1 = packbf(v0.z, v0.w);
    uint h2 = packbf(v1.x, v1.y), h3 = packbf(v1.z, v1.w);
    uint l0 = packlo(v0.x, v0.y, h0), l1 = packlo(v0.z, v0.w, h1);
    uint l2 = packlo(v1.x, v1.y, h2), l3 = packlo(v1.z, v1.w, h3);
    hi[i] = make_uint4(h0, h1, h2, h3);
    lo[i] = make_uint4(l0, l1, l2, l3);
}

// ---------------- shared mma plumbing ----------------
__device__ __forceinline__ uint smem_u32(const void* p) {
    uint a;
    asm("{ .reg .u64 t; cvta.to.shared.u64 t, %1; cvt.u32.u64 %0, t; }"
        : "=r"(a) : "l"(p));
    return a;
}

#define LDSM4(r, addr) \
    asm volatile("ldmatrix.sync.aligned.m8n8.x4.shared.b16 {%0,%1,%2,%3}, [%4];" \
        : "=r"((r)[0]), "=r"((r)[1]), "=r"((r)[2]), "=r"((r)[3]) : "r"(addr))

#define MMA16816(d, a, b0, b1v) \
    asm volatile("mma.sync.aligned.m16n8k16.row.col.f32.bf16.bf16.f32 " \
        "{%0,%1,%2,%3}, {%4,%5,%6,%7}, {%8,%9}, {%0,%1,%2,%3};" \
        : "+f"((d)[0]), "+f"((d)[1]), "+f"((d)[2]), "+f"((d)[3]) \
        : "r"((a)[0]), "r"((a)[1]), "r"((a)[2]), "r"((a)[3]), "r"(b0), "r"(b1v))

#define STS128U(addr, a, b, c, d) \
    asm volatile("st.shared.v4.b32 [%0], {%1, %2, %3, %4};" \
                 :: "r"(addr), "r"(a), "r"(b), "r"(c), "r"(d) : "memory")

#define CPASYNC16(saddr, gptr) \
    asm volatile("cp.async.cg.shared.global [%0], [%1], 16;" \
                 :: "r"((uint)(saddr)), "l"(gptr) : "memory")
#define CPCOMMIT() asm volatile("cp.async.commit_group;" ::: "memory")
#define CPWAIT1()  asm volatile("cp.async.wait_group 1;" ::: "memory")
#define CPWAIT0()  asm volatile("cp.async.wait_group 0;" ::: "memory")

// ---------------- mma.sync bf16x3 GEMM, cp.async 3-stage ----------------
#define GSTR 40
#define TBLK (128*GSTR)
#define TBLKB (TBLK*2)
#define NSTAGE 3
#define GEMM_SMEM (NSTAGE*4*TBLKB)     // 122880 B

__global__ __launch_bounds__(256) void mma_gemm_kernel(
    const __nv_bfloat16* __restrict__ Ah, const __nv_bfloat16* __restrict__ Al,
    const __nv_bfloat16* __restrict__ Wh, const __nv_bfloat16* __restrict__ Wl,
    const float* __restrict__ b1, const float* __restrict__ b2,
    float* __restrict__ out, int N, int K)
{
    extern __shared__ char gsm[];
    const uint sbase = smem_u32(gsm);
    const int tid  = threadIdx.x;
    const int warp = tid >> 5;
    const int lane = tid & 31;
    const int c0 = blockIdx.x * 128;
    const int r0 = blockIdx.y * 128;
    const int wm = warp >> 2;
    const int wn = warp & 3;

    const int lr = tid & 127;
    const __nv_bfloat16* gh0 = (tid < 128) ? (Ah + (size_t)(r0 + lr) * K)
                                           : (Wh + (size_t)(c0 + lr) * K);
    const __nv_bfloat16* gl0 = (tid < 128) ? (Al + (size_t)(r0 + lr) * K)
                                           : (Wl + (size_t)(c0 + lr) * K);
    const uint sdst_h = (tid < 128 ? 0u : 2u*TBLKB) + (uint)lr * (GSTR*2);

    const uint aoff = (((lane & 7) + ((lane >> 3) & 1) * 8) * GSTR
                       + (lane >> 4) * 8) * 2;
    const uint boff = (((lane & 7) + (lane >> 4) * 8) * GSTR
                       + ((lane >> 3) & 1) * 8) * 2;

    float acc[4][4][4];
    #pragma unroll
    for (int m = 0; m < 4; m++)
        #pragma unroll
        for (int n = 0; n < 4; n++)
            #pragma unroll
            for (int q = 0; q < 4; q++) acc[m][n][q] = 0.f;

    const int nk = K / 32;

    // async stage loader: issues 8x cp.async(16B) + commit
    auto loadStageAsync = [&](int kt, int s) {
        const __nv_bfloat16* gh = gh0 + kt * 32;
        const __nv_bfloat16* gl = gl0 + kt * 32;
        uint bh = sbase + (uint)s * (4*TBLKB) + sdst_h;
        uint bl = bh + TBLKB;
        CPASYNC16(bh +  0, gh);
        CPASYNC16(bh + 16, gh + 8);
        CPASYNC16(bh + 32, gh + 16);
        CPASYNC16(bh + 48, gh + 24);
        CPASYNC16(bl +  0, gl);
        CPASYNC16(bl + 16, gl + 8);
        CPASYNC16(bl + 32, gl + 16);
        CPASYNC16(bl + 48, gl + 24);
        CPCOMMIT();
    };

    loadStageAsync(0, 0);
    loadStageAsync(1, 1);

    for (int kt = 0; kt < nk; kt++) {
        const int s = kt % NSTAGE;
        if (kt + 1 < nk) { CPWAIT1(); } else { CPWAIT0(); }
        __syncthreads();
        if (kt + 2 < nk) loadStageAsync(kt + 2, (kt + 2) % NSTAGE);

        const uint sb = sbase + (uint)s * (4*TBLKB);
        #pragma unroll
        for (int kb = 0; kb < 2; kb++) {
            const uint kbb = (uint)kb * 32;
            uint ah[4][4], al[4][4], bhf[2][4], blf[2][4];
            #pragma unroll
            for (int mt = 0; mt < 4; mt++) {
                uint ab = sb + ((uint)(wm*64 + mt*16) * GSTR) * 2 + kbb + aoff;
                LDSM4(ah[mt], ab);
                LDSM4(al[mt], ab + TBLKB);
            }
            #pragma unroll
            for (int nt2 = 0; nt2 < 2; nt2++) {
                uint bb = sb + 2u*TBLKB
                        + ((uint)(wn*32 + nt2*16) * GSTR) * 2 + kbb + boff;
                LDSM4(bhf[nt2], bb);
                LDSM4(blf[nt2], bb + TBLKB);
            }
            #pragma unroll
            for (int mt = 0; mt < 4; mt++)
                #pragma unroll
                for (int nt = 0; nt < 4; nt++) {
                    uint* bp = bhf[nt >> 1];
                    MMA16816(acc[mt][nt], ah[mt], bp[(nt & 1) * 2], bp[(nt & 1) * 2 + 1]);
                }
            #pragma unroll
            for (int mt = 0; mt < 4; mt++)
                #pragma unroll
                for (int nt = 0; nt < 4; nt++) {
                    uint* bp = blf[nt >> 1];
                    MMA16816(acc[mt][nt], ah[mt], bp[(nt & 1) * 2], bp[(nt & 1) * 2 + 1]);
                }
            #pragma unroll
            for (int mt = 0; mt < 4; mt++)
                #pragma unroll
                for (int nt = 0; nt < 4; nt++) {
                    uint* bp = bhf[nt >> 1];
                    MMA16816(acc[mt][nt], al[mt], bp[(nt & 1) * 2], bp[(nt & 1) * 2 + 1]);
                }
        }
    }

    const int rowb = r0 + wm*64 + (lane >> 2);
    const int colb = c0 + wn*32 + (lane & 3) * 2;
    #pragma unroll
    for (int nt = 0; nt < 4; nt++) {
        int col = colb + nt * 8;
        float bv0 = b1[col]     + (b2 ? b2[col]     : 0.f);
        float bv1 = b1[col + 1] + (b2 ? b2[col + 1] : 0.f);
        #pragma unroll
        for (int mt = 0; mt < 4; mt++) {
            int row = rowb + mt * 16;
            float2 o0 = make_float2(acc[mt][nt][0] + bv0, acc[mt][nt][1] + bv1);
            float2 o1 = make_float2(acc[mt][nt][2] + bv0, acc[mt][nt][3] + bv1);
            *(float2*)(out + (size_t)row * N + col)       = o0;
            *(float2*)(out + (size_t)(row + 8) * N + col) = o1;
        }
    }
}

// ------------- persistent recurrence, tensor-core + register-W -------------
// Identical to r12 except h staging uses cp.async (no LDG->reg->STS round trip).
__global__ __launch_bounds__(1024) void rnn_mma_kernel(
    const float* __restrict__ xw,
    __nv_bfloat16* __restrict__ yh, __nv_bfloat16* __restrict__ yl,
    float* __restrict__ yfp, const float* __restrict__ Whh, int nsteps)
{
    extern __shared__ char smemc[];
    const uint hbase = smem_u32(smemc);
    float* redf = (float*)(smemc + RED_OFF);   // [28 warps][32 lanes][4]

    const int tid = threadIdx.x;
    const int bid = blockIdx.x;
    const int cg  = bid & 31;
    const int bg  = bid >> 5;
    const int c0  = cg * 32;
    const int warp = tid >> 5;
    const int lane = tid & 31;
    const int kg  = warp >> 2;       // k-split 0..7 (128 k each)
    const int nt  = warp & 3;        // n-tile 0..3 (8 cols each)

    unsigned* cnt = &g_cnt4[bg*64];
    unsigned* gen = &g_gen4[bg*64];
    unsigned gen0 = ld_relaxed(gen);

    // ---- one-time: W B-fragments into registers (bf16 hi/lo) ----
    const int nW = c0 + nt*8 + (lane >> 2);
    const int kW = kg*128 + 2*(lane & 3);
    uint whi0[8], whi1[8], wlo0[8], wlo1[8];
    #pragma unroll
    for (int kt = 0; kt < 8; kt++) {
        const float* wp = Whh + (size_t)nW * HH + kW + kt*16;
        float2 w0 = *(const float2*)(wp);
        float2 w1 = *(const float2*)(wp + 8);
        whi0[kt] = packbf(w0.x, w0.y); wlo0[kt] = packlo(w0.x, w0.y, whi0[kt]);
        whi1[kt] = packbf(w1.x, w1.y); wlo1[kt] = packlo(w1.x, w1.y, whi1[kt]);
    }

    // staging: thread -> 16 k of one batch row (hi + lo), via cp.async
    const int sb  = tid & 15;
    const int skc = tid >> 4;        // 0..63
    const uint sdst = hbase + (uint)sb * (HSTR*2) + (uint)skc * 32;

    // ldmatrix A offset
    const uint aoff = (uint)(((lane & 7) + ((lane >> 3) & 1) * 8) * (HSTR*2)
                             + (lane >> 4) * 16);

    // epilogue mapping (D-frag)
    const int erow = bg*16 + (lane >> 2);
    const int ecol = c0 + nt*8 + (lane & 3)*2;

    for (int t = 0; t < nsteps; t++) {
        // stage h (hi/lo bf16) from slot t  (issue ASAP after barrier)
        {
            const __nv_bfloat16* sh = yh + (size_t)t*BBHH
                                      + (size_t)(bg*16 + sb)*HH + skc*16;
            const __nv_bfloat16* sl = yl + (size_t)t*BBHH
                                      + (size_t)(bg*16 + sb)*HH + skc*16;
            CPASYNC16(sdst,      sh);
            CPASYNC16(sdst + 16, sh + 8);
            CPASYNC16(sdst + HS_BYTES,      sl);
            CPASYNC16(sdst + HS_BYTES + 16, sl + 8);
            CPCOMMIT();
        }

        // prefetch xw for epilogue (reducing warps only)
        size_t idx0 = ((size_t)t*BB + erow)*HH + ecol;
        float2 xw0, xw8;
        if (kg == 0) {
            xw0 = *(const float2*)&xw[idx0];
            xw8 = *(const float2*)&xw[idx0 + 8*HH];
        }

        CPWAIT0();
        __syncthreads();

        float acc[4] = {0.f, 0.f, 0.f, 0.f};
        #pragma unroll
        for (int kt = 0; kt < 8; kt++) {
            uint ab = hbase + (uint)((kg*128 + kt*16) * 2) + aoff;
            uint Ah[4], Al[4];
            LDSM4(Ah, ab);
            MMA16816(acc, Ah, whi0[kt], whi1[kt]);   // Ah*Wh
            MMA16816(acc, Ah, wlo0[kt], wlo1[kt]);   // Ah*Wl
            LDSM4(Al, ab + HS_BYTES);
            MMA16816(acc, Al, whi0[kt], whi1[kt]);   // Al*Wh
        }

        // k-split reduction via smem (warps kg>0 store; kg==0 reduces)
        if (kg) *(float4*)(redf + (warp - 4)*128 + lane*4) = *(float4*)acc;
        __syncthreads();
        if (kg == 0) {
            #pragma unroll
            for (int k = 1; k < 8; k++) {
                float4 o = *(float4*)(redf + (k*4 + nt - 4)*128 + lane*4);
                acc[0] += o.x; acc[1] += o.y; acc[2] += o.z; acc[3] += o.w;
            }
            float t0 = tanhf(xw0.x + acc[0]);
            float t1 = tanhf(xw0.y + acc[1]);
            float t2 = tanhf(xw8.x + acc[2]);
            float t3 = tanhf(xw8.y + acc[3]);
            uint h01 = packbf(t0, t1), l01 = packlo(t0, t1, h01);
            uint h23 = packbf(t2, t3), l23 = packlo(t2, t3, h23);
            size_t o0 = idx0 + BBHH;          // slot t+1
            *(uint*)&yh[o0]          = h01;
            *(uint*)&yl[o0]          = l01;
            *(uint*)&yh[o0 + 8*HH]   = h23;
            *(uint*)&yl[o0 + 8*HH]   = l23;
            if (t == nsteps - 1) {
                *(float2*)&yfp[idx0]          = make_float2(t0, t1);
                *(float2*)&yfp[idx0 + 8*HH]   = make_float2(t2, t3);
            }
        }

        group_sync(cnt, gen, gen0 + (unsigned)t + 1u);
    }
}

// ------------- hidden-state gather ----------------
__global__ void gather_hidden_kernel(float* __restrict__ out_hidden)
{
    int i = blockIdx.x * blockDim.x + threadIdx.x;
    const float* src = (i < BBHH)
        ? (g_y0 + (size_t)(TT-1)*BBHH + i)
        : (g_y1 + (size_t)(TT-1)*BBHH + (i - BBHH));
    out_hidden[i] = *src;
}

extern "C" void kernel_launch(void* const* d_in, const int* in_sizes, int n_in,
                              void* d_out, int out_size) {
    const float* x     = (const float*)d_in[0];
    const float* h0    = (const float*)d_in[1];
    const float* w_ih0 = (const float*)d_in[2];
    const float* w_hh0 = (const float*)d_in[3];
    const float* b_ih0 = (const float*)d_in[4];
    const float* b_hh0 = (const float*)d_in[5];
    const float* w_ih1 = (const float*)d_in[6];
    const float* w_hh1 = (const float*)d_in[7];
    const float* b_ih1 = (const float*)d_in[8];
    const float* b_hh1 = (const float*)d_in[9];
    const float* w_dec = (const float*)d_in[10];
    const float* b_dec = (const float*)d_in[11];
    float* out = (float*)d_out;

    cudaFuncSetAttribute(rnn_mma_kernel,
                         cudaFuncAttributeMaxDynamicSharedMemorySize, RNN2_SMEM);
    cudaFuncSetAttribute(mma_gemm_kernel,
                         cudaFuncAttributeMaxDynamicSharedMemorySize, GEMM_SMEM);

    float* xw;  cudaGetSymbolAddress((void**)&xw,  g_xw);
    float* y0;  cudaGetSymbolAddress((void**)&y0,  g_y0);
    float* y1;  cudaGetSymbolAddress((void**)&y1,  g_y1);
    __nv_bfloat16 *ah, *al, *wh, *wl, *y0h, *y0l, *y1h, *y1l;
    cudaGetSymbolAddress((void**)&ah,  g_ah);
    cudaGetSymbolAddress((void**)&al,  g_al);
    cudaGetSymbolAddress((void**)&wh,  g_wh);
    cudaGetSymbolAddress((void**)&wl,  g_wl);
    cudaGetSymbolAddress((void**)&y0h, g_y0h);
    cudaGetSymbolAddress((void**)&y0l, g_y0l);
    cudaGetSymbolAddress((void**)&y1h, g_y1h);
    cudaGetSymbolAddress((void**)&y1l, g_y1l);

    // 0) split x, w_ih0, and both h0 slices (h0 -> slot 0 of yh/yl arrays)
    cvt_split_kernel<<<RR*CC/8/256, 256>>>((const float4*)x, (uint4*)ah, (uint4*)al, RR*CC/8);
    cvt_split_kernel<<<HH*CC/8/256, 256>>>((const float4*)w_ih0, (uint4*)wh, (uint4*)wl, HH*CC/8);
    cvt_split_kernel<<<BBHH/8/256, 256>>>((const float4*)h0, (uint4*)y0h, (uint4*)y0l, BBHH/8);
    cvt_split_kernel<<<BBHH/8/256, 256>>>((const float4*)(h0 + BBHH), (uint4*)y1h, (uint4*)y1l, BBHH/8);

    // 1) layer-0 input projection: xw = x @ w_ih0^T + b_ih0 + b_hh0
    {
        dim3 grid(HH/128, RR/128);
        mma_gemm_kernel<<<grid, 256, GEMM_SMEM>>>(ah, al, wh, wl, b_ih0, b_hh0, xw, HH, CC);
    }
    // 2) layer-0 recurrence
    rnn_mma_kernel<<<NB_RNN, 1024, RNN2_SMEM>>>(xw, y0h, y0l, y0, w_hh0, TT);
    // 3) layer-1 input projection (A = y0 hi/lo slots 1..512 directly)
    cvt_split_kernel<<<HH*HH/8/256, 256>>>((const float4*)w_ih1, (uint4*)wh, (uint4*)wl, HH*HH/8);
    {
        dim3 grid(HH/128, RR/128);
        mma_gemm_kernel<<<grid, 256, GEMM_SMEM>>>(y0h + BBHH, y0l + BBHH, wh, wl,
                                                  b_ih1, b_hh1, xw, HH, HH);
    }
    // 4) layer-1 recurrence
    rnn_mma_kernel<<<NB_RNN, 1024, RNN2_SMEM>>>(xw, y1h, y1l, y1, w_hh1, TT);
    // 5) decoder (A = y1 hi/lo slots 1..512)
    cvt_split_kernel<<<CC*HH/8/256, 256>>>((const float4*)w_dec, (uint4*)wh, (uint4*)wl, CC*HH/8);
    {
        dim3 grid(CC/128, RR/128);
        mma_gemm_kernel<<<grid, 256, GEMM_SMEM>>>(y1h + BBHH, y1l + BBHH, wh, wl,
                                                  b_dec, nullptr, out, CC, HH);
    }
    // 6) hidden states appended after decoded
    gather_hidden_kernel<<<(2*BBHH)/256, 256>>>(out + (size_t)TT*BB*CC);
}